// round 1
// baseline (speedup 1.0000x reference)
#include <cuda_runtime.h>

// ---- problem constants (from metadata) ----
#define TT    4
#define NTOK  8192
#define DD    1024
#define EE    8
#define EFF   512
#define TOPK  2

// ---- tiling ----
#define MTOK  32              // tokens per tile
#define RWS   (MTOK*TT)       // 128 rows per tile
#define KB    32              // K chunk
#define ASTR  (RWS + 2)       // 130, even (8B-aligned row pairs), conflict pad
#define BSTR  (2*128 + 2)     // 258, duplicated B columns + pad
#define CAP   (NTOK*TOPK)     // 16384 assignments max
#define MAXTILES (CAP/MTOK)   // 512
#define SMEM_BYTES ((KB*ASTR + KB*BSTR)*4)   // 49,664 B

typedef unsigned long long ull;

// ---- device scratch (no allocations allowed) ----
__device__ int g_count[EE];
__device__ int g_list[EE*CAP];                       // packed (n<<1)|k per expert
__device__ unsigned char g_spk[(size_t)CAP*TT*EFF];  // 32MB: hidden spikes per slot

static __device__ __forceinline__ ull fma2(ull a, ull b, ull c) {
    ull d;
    asm("fma.rn.f32x2 %0, %1, %2, %3;" : "=l"(d) : "l"(a), "l"(b), "l"(c));
    return d;
}
static __device__ __forceinline__ void unpk(ull v, float &lo, float &hi) {
    asm("mov.b64 {%0, %1}, %2;" : "=f"(lo), "=f"(hi) : "l"(v));
}

static __device__ __forceinline__ void lif4(float v0, float v1, float v2, float v3,
                                            float &s0, float &s1, float &s2, float &s3) {
    float mem = v0;                                  // 0.9*0 + v0
    s0 = (mem > 1.0f) ? 1.0f : 0.0f; mem -= s0;
    mem = 0.9f*mem + v1; s1 = (mem > 1.0f) ? 1.0f : 0.0f; mem -= s1;
    mem = 0.9f*mem + v2; s2 = (mem > 1.0f) ? 1.0f : 0.0f; mem -= s2;
    mem = 0.9f*mem + v3; s3 = (mem > 1.0f) ? 1.0f : 0.0f; mem -= s3;
}

// Shared 128x128 (per chunk) GEMM core. Accumulator pairs packed along ROWS:
// acc[jj][j] holds rows (8*ty+2j, 8*ty+2j+1) at column (tx + 16*jj).
// A is natural layout As[k][row] (row pairs contiguous -> LDS.64),
// B is duplicated Bs[k][2c]=Bs[k][2c+1]=B[c][k] (broadcast pair -> LDS.64).
static __device__ __forceinline__ void gemm_chunk(const float* __restrict__ As,
                                                  const float* __restrict__ Bs,
                                                  int tx, int ty, ull acc[8][4]) {
    #pragma unroll
    for (int kk = 0; kk < KB; ++kk) {
        const float* Ak = As + kk*ASTR + ty*8;
        const float* Bk = Bs + kk*BSTR + 2*tx;
        ull a[4];
        #pragma unroll
        for (int j = 0; j < 4; ++j) a[j] = *(const ull*)(Ak + 2*j);
        #pragma unroll
        for (int jj = 0; jj < 8; ++jj) {
            ull b = *(const ull*)(Bk + 32*jj);
            #pragma unroll
            for (int j = 0; j < 4; ++j) acc[jj][j] = fma2(a[j], b, acc[jj][j]);
        }
    }
}

__global__ void reset_kernel() {
    if (threadIdx.x < EE) g_count[threadIdx.x] = 0;
}

__global__ void route_kernel(const int* __restrict__ idx) {
    int n = blockIdx.x * blockDim.x + threadIdx.x;
    if (n >= NTOK) return;
    #pragma unroll
    for (int k = 0; k < TOPK; ++k) {
        int e = idx[n*TOPK + k];
        int p = atomicAdd(&g_count[e], 1);
        g_list[e*CAP + p] = (n << 1) | k;
    }
}

extern __shared__ float smem[];

// ---------------- stage 1: h = LIF(x @ up_w^T), spikes -> g_spk ----------------
__global__ __launch_bounds__(256, 2)
void stage1_kernel(const float* __restrict__ x, const float* __restrict__ up_w) {
    const int e = blockIdx.y;
    const int cnt = g_count[e];
    const int start = blockIdx.x * MTOK;
    if (start >= cnt) return;

    float* As = smem;               // [KB][ASTR]
    float* Bs = smem + KB*ASTR;     // [KB][BSTR]

    __shared__ int s_ent[MTOK];
    __shared__ int s_ok[MTOK];
    __shared__ int s_rb[RWS];

    const int tid = threadIdx.x;
    if (tid < MTOK) {
        int i = start + tid;
        int ok = (i < cnt) ? 1 : 0;
        int ent = g_list[e*CAP + (ok ? i : start)];
        s_ent[tid] = ent;
        s_ok[tid] = ok;
    }
    __syncthreads();
    if (tid < RWS) {
        int ent = s_ent[tid >> 2];
        int n = ent >> 1;
        int t = tid & 3;
        s_rb[tid] = (t * NTOK + n) * DD;
    }
    __syncthreads();

    const int tx = tid & 15, ty = tid >> 4;
    const float* Ue = up_w + (size_t)e * EFF * DD;

    for (int fc = 0; fc < EFF/128; ++fc) {
        ull acc[8][4];
        #pragma unroll
        for (int jj = 0; jj < 8; ++jj)
            #pragma unroll
            for (int j = 0; j < 4; ++j) acc[jj][j] = 0ull;

        for (int kc = 0; kc < DD/KB; ++kc) {
            const int kbase = kc * KB;
            // stage A: x rows (gathered), coalesced along k
            #pragma unroll
            for (int u = 0; u < 4; ++u) {
                int q = tid + u*256;
                int r = q >> 3, kq = (q & 7) << 2;
                float4 v = *(const float4*)(x + s_rb[r] + kbase + kq);
                As[(kq+0)*ASTR + r] = v.x;
                As[(kq+1)*ASTR + r] = v.y;
                As[(kq+2)*ASTR + r] = v.z;
                As[(kq+3)*ASTR + r] = v.w;
            }
            // stage B: up_w rows, duplicated pairs
            #pragma unroll
            for (int u = 0; u < 4; ++u) {
                int q = tid + u*256;
                int f = q >> 3, kq = (q & 7) << 2;
                float4 v = *(const float4*)(Ue + (size_t)(fc*128 + f)*DD + kbase + kq);
                float* b0 = Bs + (kq+0)*BSTR + 2*f; b0[0] = v.x; b0[1] = v.x;
                float* b1 = Bs + (kq+1)*BSTR + 2*f; b1[0] = v.y; b1[1] = v.y;
                float* b2 = Bs + (kq+2)*BSTR + 2*f; b2[0] = v.z; b2[1] = v.z;
                float* b3 = Bs + (kq+3)*BSTR + 2*f; b3[0] = v.w; b3[1] = v.w;
            }
            __syncthreads();
            gemm_chunk(As, Bs, tx, ty, acc);
            __syncthreads();
        }

        // epilogue: LIF over t (rows of same token are in-thread), store spikes
        #pragma unroll
        for (int h = 0; h < 2; ++h) {
            int tl = ty*2 + h;
            if (!s_ok[tl]) continue;
            int slot = s_ent[tl];
            unsigned char* base = g_spk + (size_t)slot * (TT*EFF);
            #pragma unroll
            for (int jj = 0; jj < 8; ++jj) {
                int c = fc*128 + tx + 16*jj;
                float v0, v1, v2, v3, s0, s1, s2, s3;
                unpk(acc[jj][h*2+0], v0, v1);
                unpk(acc[jj][h*2+1], v2, v3);
                lif4(v0, v1, v2, v3, s0, s1, s2, s3);
                base[c +   0] = (unsigned char)s0;
                base[c + 512] = (unsigned char)s1;
                base[c + 1024] = (unsigned char)s2;
                base[c + 1536] = (unsigned char)s3;
            }
        }
    }
}

// ---------------- stage 2: o = LIF(spk @ down_w^T) * w -> atomicAdd out ----------------
__global__ __launch_bounds__(256, 2)
void stage2_kernel(const float* __restrict__ down_w, const float* __restrict__ ew,
                   float* __restrict__ out) {
    const int e = blockIdx.y;
    const int cnt = g_count[e];
    const int start = blockIdx.x * MTOK;
    if (start >= cnt) return;

    float* As = smem;
    float* Bs = smem + KB*ASTR;

    __shared__ int   s_ent[MTOK];
    __shared__ int   s_ok[MTOK];
    __shared__ float s_w[MTOK];

    const int tid = threadIdx.x;
    if (tid < MTOK) {
        int i = start + tid;
        int ok = (i < cnt) ? 1 : 0;
        int ent = g_list[e*CAP + (ok ? i : start)];
        s_ent[tid] = ent;
        s_ok[tid] = ok;
        s_w[tid] = ew[ent];   // expert_weights flat index == slot
    }
    __syncthreads();

    const int tx = tid & 15, ty = tid >> 4;
    const float* We = down_w + (size_t)e * DD * EFF;

    for (int dc = 0; dc < DD/128; ++dc) {
        ull acc[8][4];
        #pragma unroll
        for (int jj = 0; jj < 8; ++jj)
            #pragma unroll
            for (int j = 0; j < 4; ++j) acc[jj][j] = 0ull;

        for (int kc = 0; kc < EFF/KB; ++kc) {
            const int kbase = kc * KB;
            // stage A: spikes (uint8 -> float, exact)
            #pragma unroll
            for (int u = 0; u < 4; ++u) {
                int q = tid + u*256;
                int r = q >> 3, kq = (q & 7) << 2;
                int tl = r >> 2, t = r & 3;
                const uchar4 v = *(const uchar4*)(g_spk + (size_t)s_ent[tl]*(TT*EFF)
                                                  + t*EFF + kbase + kq);
                As[(kq+0)*ASTR + r] = (float)v.x;
                As[(kq+1)*ASTR + r] = (float)v.y;
                As[(kq+2)*ASTR + r] = (float)v.z;
                As[(kq+3)*ASTR + r] = (float)v.w;
            }
            // stage B: down_w rows, duplicated pairs
            #pragma unroll
            for (int u = 0; u < 4; ++u) {
                int q = tid + u*256;
                int d = q >> 3, kq = (q & 7) << 2;
                float4 v = *(const float4*)(We + (size_t)(dc*128 + d)*EFF + kbase + kq);
                float* b0 = Bs + (kq+0)*BSTR + 2*d; b0[0] = v.x; b0[1] = v.x;
                float* b1 = Bs + (kq+1)*BSTR + 2*d; b1[0] = v.y; b1[1] = v.y;
                float* b2 = Bs + (kq+2)*BSTR + 2*d; b2[0] = v.z; b2[1] = v.z;
                float* b3 = Bs + (kq+3)*BSTR + 2*d; b3[0] = v.w; b3[1] = v.w;
            }
            __syncthreads();
            gemm_chunk(As, Bs, tx, ty, acc);
            __syncthreads();
        }

        // epilogue: LIF, weight, spike-gated atomic accumulate (<=2 adds/elem, commutative)
        #pragma unroll
        for (int h = 0; h < 2; ++h) {
            int tl = ty*2 + h;
            if (!s_ok[tl]) continue;
            int n = s_ent[tl] >> 1;
            float w = s_w[tl];
            #pragma unroll
            for (int jj = 0; jj < 8; ++jj) {
                int d = dc*128 + tx + 16*jj;
                float v0, v1, v2, v3, s0, s1, s2, s3;
                unpk(acc[jj][h*2+0], v0, v1);
                unpk(acc[jj][h*2+1], v2, v3);
                lif4(v0, v1, v2, v3, s0, s1, s2, s3);
                if (s0 != 0.0f) atomicAdd(out + (0*NTOK + n)*DD + d, w);
                if (s1 != 0.0f) atomicAdd(out + (1*NTOK + n)*DD + d, w);
                if (s2 != 0.0f) atomicAdd(out + (2*NTOK + n)*DD + d, w);
                if (s3 != 0.0f) atomicAdd(out + (3*NTOK + n)*DD + d, w);
            }
        }
    }
}

extern "C" void kernel_launch(void* const* d_in, const int* in_sizes, int n_in,
                              void* d_out, int out_size) {
    const float* x  = (const float*)d_in[0];
    const int*   ei = (const int*)  d_in[1];
    const float* ew = (const float*)d_in[2];
    const float* up = (const float*)d_in[3];
    const float* dw = (const float*)d_in[4];
    float* out = (float*)d_out;
    (void)in_sizes; (void)n_in;

    cudaFuncSetAttribute(stage1_kernel, cudaFuncAttributeMaxDynamicSharedMemorySize, SMEM_BYTES);
    cudaFuncSetAttribute(stage2_kernel, cudaFuncAttributeMaxDynamicSharedMemorySize, SMEM_BYTES);

    cudaMemsetAsync(d_out, 0, (size_t)out_size * sizeof(float), 0);
    reset_kernel<<<1, 32>>>();
    route_kernel<<<NTOK/256, 256>>>(ei);
    dim3 grid(MAXTILES, EE);
    stage1_kernel<<<grid, 256, SMEM_BYTES>>>(x, up);
    stage2_kernel<<<grid, 256, SMEM_BYTES>>>(dw, ew, out);
}

// round 2
// speedup vs baseline: 1.0037x; 1.0037x over previous
#include <cuda_runtime.h>

// ---- problem constants (from metadata) ----
#define TT    4
#define NTOK  8192
#define DD    1024
#define EE    8
#define EFF   512
#define TOPK  2

// ---- tiling ----
#define MTOK  32              // tokens per tile
#define RWS   (MTOK*TT)       // 128 rows per tile
#define KB    32              // K chunk
#define ASTR  (RWS + 2)       // 130, even (8B-aligned row pairs), conflict pad
#define BSTR  (2*128 + 2)     // 258, duplicated B columns + pad
#define CAP   (NTOK*TOPK)     // 16384 assignments max
#define MAXTILES (CAP/MTOK)   // 512
#define SMEM_BYTES ((KB*ASTR + KB*BSTR)*4)   // 49,664 B

typedef unsigned long long ull;

// ---- device scratch (no allocations allowed) ----
__device__ int g_count[EE];
__device__ int g_list[EE*CAP];                       // packed (n<<1)|k per expert
__device__ unsigned char g_spk[(size_t)CAP*TT*EFF];  // 32MB: hidden spikes per slot

static __device__ __forceinline__ ull fma2(ull a, ull b, ull c) {
    ull d;
    asm("fma.rn.f32x2 %0, %1, %2, %3;" : "=l"(d) : "l"(a), "l"(b), "l"(c));
    return d;
}
static __device__ __forceinline__ void unpk(ull v, float &lo, float &hi) {
    asm("mov.b64 {%0, %1}, %2;" : "=f"(lo), "=f"(hi) : "l"(v));
}

static __device__ __forceinline__ void lif4(float v0, float v1, float v2, float v3,
                                            float &s0, float &s1, float &s2, float &s3) {
    float mem = v0;                                  // 0.9*0 + v0
    s0 = (mem > 1.0f) ? 1.0f : 0.0f; mem -= s0;
    mem = 0.9f*mem + v1; s1 = (mem > 1.0f) ? 1.0f : 0.0f; mem -= s1;
    mem = 0.9f*mem + v2; s2 = (mem > 1.0f) ? 1.0f : 0.0f; mem -= s2;
    mem = 0.9f*mem + v3; s3 = (mem > 1.0f) ? 1.0f : 0.0f; mem -= s3;
}

// Shared 128x128 (per chunk) GEMM core. Accumulator pairs packed along ROWS:
// acc[jj][j] holds rows (8*ty+2j, 8*ty+2j+1) at column (tx + 16*jj).
// A is natural layout As[k][row] (row pairs contiguous -> LDS.64),
// B is duplicated Bs[k][2c]=Bs[k][2c+1]=B[c][k] (broadcast pair -> LDS.64).
static __device__ __forceinline__ void gemm_chunk(const float* __restrict__ As,
                                                  const float* __restrict__ Bs,
                                                  int tx, int ty, ull acc[8][4]) {
    #pragma unroll
    for (int kk = 0; kk < KB; ++kk) {
        const float* Ak = As + kk*ASTR + ty*8;
        const float* Bk = Bs + kk*BSTR + 2*tx;
        ull a[4];
        #pragma unroll
        for (int j = 0; j < 4; ++j) a[j] = *(const ull*)(Ak + 2*j);
        #pragma unroll
        for (int jj = 0; jj < 8; ++jj) {
            ull b = *(const ull*)(Bk + 32*jj);
            #pragma unroll
            for (int j = 0; j < 4; ++j) acc[jj][j] = fma2(a[j], b, acc[jj][j]);
        }
    }
}

__global__ void reset_kernel() {
    if (threadIdx.x < EE) g_count[threadIdx.x] = 0;
}

__global__ void route_kernel(const int* __restrict__ idx) {
    int n = blockIdx.x * blockDim.x + threadIdx.x;
    if (n >= NTOK) return;
    #pragma unroll
    for (int k = 0; k < TOPK; ++k) {
        int e = idx[n*TOPK + k];
        int p = atomicAdd(&g_count[e], 1);
        g_list[e*CAP + p] = (n << 1) | k;
    }
}

extern __shared__ float smem[];

// ---------------- stage 1: h = LIF(x @ up_w^T), spikes -> g_spk ----------------
__global__ __launch_bounds__(256, 2)
void stage1_kernel(const float* __restrict__ x, const float* __restrict__ up_w) {
    const int e = blockIdx.y;
    const int cnt = g_count[e];
    const int start = blockIdx.x * MTOK;
    if (start >= cnt) return;

    float* As = smem;               // [KB][ASTR]
    float* Bs = smem + KB*ASTR;     // [KB][BSTR]

    __shared__ int s_ent[MTOK];
    __shared__ int s_ok[MTOK];
    __shared__ int s_rb[RWS];

    const int tid = threadIdx.x;
    if (tid < MTOK) {
        int i = start + tid;
        int ok = (i < cnt) ? 1 : 0;
        int ent = g_list[e*CAP + (ok ? i : start)];
        s_ent[tid] = ent;
        s_ok[tid] = ok;
    }
    __syncthreads();
    if (tid < RWS) {
        int ent = s_ent[tid >> 2];
        int n = ent >> 1;
        int t = tid & 3;
        s_rb[tid] = (t * NTOK + n) * DD;
    }
    __syncthreads();

    const int tx = tid & 15, ty = tid >> 4;
    const float* Ue = up_w + (size_t)e * EFF * DD;

    for (int fc = 0; fc < EFF/128; ++fc) {
        ull acc[8][4];
        #pragma unroll
        for (int jj = 0; jj < 8; ++jj)
            #pragma unroll
            for (int j = 0; j < 4; ++j) acc[jj][j] = 0ull;

        for (int kc = 0; kc < DD/KB; ++kc) {
            const int kbase = kc * KB;
            // stage A: x rows (gathered), coalesced along k
            #pragma unroll
            for (int u = 0; u < 4; ++u) {
                int q = tid + u*256;
                int r = q >> 3, kq = (q & 7) << 2;
                float4 v = *(const float4*)(x + s_rb[r] + kbase + kq);
                As[(kq+0)*ASTR + r] = v.x;
                As[(kq+1)*ASTR + r] = v.y;
                As[(kq+2)*ASTR + r] = v.z;
                As[(kq+3)*ASTR + r] = v.w;
            }
            // stage B: up_w rows, duplicated pairs
            #pragma unroll
            for (int u = 0; u < 4; ++u) {
                int q = tid + u*256;
                int f = q >> 3, kq = (q & 7) << 2;
                float4 v = *(const float4*)(Ue + (size_t)(fc*128 + f)*DD + kbase + kq);
                float* b0 = Bs + (kq+0)*BSTR + 2*f; b0[0] = v.x; b0[1] = v.x;
                float* b1 = Bs + (kq+1)*BSTR + 2*f; b1[0] = v.y; b1[1] = v.y;
                float* b2 = Bs + (kq+2)*BSTR + 2*f; b2[0] = v.z; b2[1] = v.z;
                float* b3 = Bs + (kq+3)*BSTR + 2*f; b3[0] = v.w; b3[1] = v.w;
            }
            __syncthreads();
            gemm_chunk(As, Bs, tx, ty, acc);
            __syncthreads();
        }

        // epilogue: LIF over t (rows of same token are in-thread), store spikes
        #pragma unroll
        for (int h = 0; h < 2; ++h) {
            int tl = ty*2 + h;
            if (!s_ok[tl]) continue;
            int slot = s_ent[tl];
            unsigned char* base = g_spk + (size_t)slot * (TT*EFF);
            #pragma unroll
            for (int jj = 0; jj < 8; ++jj) {
                int c = fc*128 + tx + 16*jj;
                float v0, v1, v2, v3, s0, s1, s2, s3;
                unpk(acc[jj][h*2+0], v0, v1);
                unpk(acc[jj][h*2+1], v2, v3);
                lif4(v0, v1, v2, v3, s0, s1, s2, s3);
                base[c +   0] = (unsigned char)s0;
                base[c + 512] = (unsigned char)s1;
                base[c + 1024] = (unsigned char)s2;
                base[c + 1536] = (unsigned char)s3;
            }
        }
    }
}

// ---------------- stage 2: o = LIF(spk @ down_w^T) * w -> atomicAdd out ----------------
__global__ __launch_bounds__(256, 2)
void stage2_kernel(const float* __restrict__ down_w, const float* __restrict__ ew,
                   float* __restrict__ out) {
    const int e = blockIdx.y;
    const int cnt = g_count[e];
    const int start = blockIdx.x * MTOK;
    if (start >= cnt) return;

    float* As = smem;
    float* Bs = smem + KB*ASTR;

    __shared__ int   s_ent[MTOK];
    __shared__ int   s_ok[MTOK];
    __shared__ float s_w[MTOK];

    const int tid = threadIdx.x;
    if (tid < MTOK) {
        int i = start + tid;
        int ok = (i < cnt) ? 1 : 0;
        int ent = g_list[e*CAP + (ok ? i : start)];
        s_ent[tid] = ent;
        s_ok[tid] = ok;
        s_w[tid] = ew[ent];   // expert_weights flat index == slot
    }
    __syncthreads();

    const int tx = tid & 15, ty = tid >> 4;
    const float* We = down_w + (size_t)e * DD * EFF;

    for (int dc = 0; dc < DD/128; ++dc) {
        ull acc[8][4];
        #pragma unroll
        for (int jj = 0; jj < 8; ++jj)
            #pragma unroll
            for (int j = 0; j < 4; ++j) acc[jj][j] = 0ull;

        for (int kc = 0; kc < EFF/KB; ++kc) {
            const int kbase = kc * KB;
            // stage A: spikes (uint8 -> float, exact)
            #pragma unroll
            for (int u = 0; u < 4; ++u) {
                int q = tid + u*256;
                int r = q >> 3, kq = (q & 7) << 2;
                int tl = r >> 2, t = r & 3;
                const uchar4 v = *(const uchar4*)(g_spk + (size_t)s_ent[tl]*(TT*EFF)
                                                  + t*EFF + kbase + kq);
                As[(kq+0)*ASTR + r] = (float)v.x;
                As[(kq+1)*ASTR + r] = (float)v.y;
                As[(kq+2)*ASTR + r] = (float)v.z;
                As[(kq+3)*ASTR + r] = (float)v.w;
            }
            // stage B: down_w rows, duplicated pairs
            #pragma unroll
            for (int u = 0; u < 4; ++u) {
                int q = tid + u*256;
                int d = q >> 3, kq = (q & 7) << 2;
                float4 v = *(const float4*)(We + (size_t)(dc*128 + d)*EFF + kbase + kq);
                float* b0 = Bs + (kq+0)*BSTR + 2*d; b0[0] = v.x; b0[1] = v.x;
                float* b1 = Bs + (kq+1)*BSTR + 2*d; b1[0] = v.y; b1[1] = v.y;
                float* b2 = Bs + (kq+2)*BSTR + 2*d; b2[0] = v.z; b2[1] = v.z;
                float* b3 = Bs + (kq+3)*BSTR + 2*d; b3[0] = v.w; b3[1] = v.w;
            }
            __syncthreads();
            gemm_chunk(As, Bs, tx, ty, acc);
            __syncthreads();
        }

        // epilogue: LIF, weight, spike-gated atomic accumulate (<=2 adds/elem, commutative)
        #pragma unroll
        for (int h = 0; h < 2; ++h) {
            int tl = ty*2 + h;
            if (!s_ok[tl]) continue;
            int n = s_ent[tl] >> 1;
            float w = s_w[tl];
            #pragma unroll
            for (int jj = 0; jj < 8; ++jj) {
                int d = dc*128 + tx + 16*jj;
                float v0, v1, v2, v3, s0, s1, s2, s3;
                unpk(acc[jj][h*2+0], v0, v1);
                unpk(acc[jj][h*2+1], v2, v3);
                lif4(v0, v1, v2, v3, s0, s1, s2, s3);
                if (s0 != 0.0f) atomicAdd(out + (0*NTOK + n)*DD + d, w);
                if (s1 != 0.0f) atomicAdd(out + (1*NTOK + n)*DD + d, w);
                if (s2 != 0.0f) atomicAdd(out + (2*NTOK + n)*DD + d, w);
                if (s3 != 0.0f) atomicAdd(out + (3*NTOK + n)*DD + d, w);
            }
        }
    }
}

extern "C" void kernel_launch(void* const* d_in, const int* in_sizes, int n_in,
                              void* d_out, int out_size) {
    const float* x  = (const float*)d_in[0];
    const int*   ei = (const int*)  d_in[1];
    const float* ew = (const float*)d_in[2];
    const float* up = (const float*)d_in[3];
    const float* dw = (const float*)d_in[4];
    float* out = (float*)d_out;
    (void)in_sizes; (void)n_in;

    cudaFuncSetAttribute(stage1_kernel, cudaFuncAttributeMaxDynamicSharedMemorySize, SMEM_BYTES);
    cudaFuncSetAttribute(stage2_kernel, cudaFuncAttributeMaxDynamicSharedMemorySize, SMEM_BYTES);

    cudaMemsetAsync(d_out, 0, (size_t)out_size * sizeof(float), 0);
    reset_kernel<<<1, 32>>>();
    route_kernel<<<NTOK/256, 256>>>(ei);
    dim3 grid(MAXTILES, EE);
    stage1_kernel<<<grid, 256, SMEM_BYTES>>>(x, up);
    stage2_kernel<<<grid, 256, SMEM_BYTES>>>(dw, ew, out);
}

// round 9
// speedup vs baseline: 1.3664x; 1.3614x over previous
#include <cuda_runtime.h>
#include <cuda_bf16.h>
#include <cstdint>

#define TT 4
#define NTOK 8192
#define DD 1024
#define EE 8
#define EFF 512
#define TOPK 2
#define CAP (NTOK*TOPK)
#define MTOK 32
#define MR 128
#define SA 40
#define TILE_B (MR*SA*2)
#define XSZ (TT*NTOK*DD)
#define USZ (EE*EFF*DD)
#define DSZ (EE*DD*EFF)
#define EPS 132
#define SMB 67584

__device__ int g_count[EE];
__device__ int g_list[EE*CAP];
__device__ __nv_bfloat16 g_xl[(size_t)3*XSZ];
__device__ __nv_bfloat16 g_uw[(size_t)3*USZ];
__device__ __nv_bfloat16 g_dw[(size_t)3*DSZ];
__device__ __nv_bfloat16 g_spk[(size_t)CAP*TT*EFF];

static __device__ __forceinline__ uint32_t s2u(const void* p) {
    uint32_t a;
    asm("{ .reg .u64 t; cvta.to.shared.u64 t, %1; cvt.u32.u64 %0, t; }" : "=r"(a) : "l"(p));
    return a;
}
#define LDSM4(r0,r1,r2,r3,addr) asm volatile( \
    "ldmatrix.sync.aligned.m8n8.x4.shared.b16 {%0,%1,%2,%3}, [%4];" \
    : "=r"(r0),"=r"(r1),"=r"(r2),"=r"(r3) : "r"(addr))
#define MMA(c, a, b) asm volatile( \
    "mma.sync.aligned.m16n8k16.row.col.f32.bf16.bf16.f32 " \
    "{%0,%1,%2,%3},{%4,%5,%6,%7},{%8,%9},{%0,%1,%2,%3};" \
    : "+f"((c)[0]),"+f"((c)[1]),"+f"((c)[2]),"+f"((c)[3]) \
    : "r"((a)[0]),"r"((a)[1]),"r"((a)[2]),"r"((a)[3]), "r"((b)[0]),"r"((b)[1]))

static __device__ __forceinline__ void lif4(float v0, float v1, float v2, float v3,
                                            float &s0, float &s1, float &s2, float &s3) {
    float m = v0;     s0 = (m > 1.0f) ? 1.0f : 0.0f; m -= s0;
    m = 0.9f*m + v1;  s1 = (m > 1.0f) ? 1.0f : 0.0f; m -= s1;
    m = 0.9f*m + v2;  s2 = (m > 1.0f) ? 1.0f : 0.0f; m -= s2;
    m = 0.9f*m + v3;  s3 = (m > 1.0f) ? 1.0f : 0.0f;
}

__global__ void reset_kernel() { if (threadIdx.x < EE) g_count[threadIdx.x] = 0; }

__global__ void route_kernel(const int* __restrict__ idx) {
    int n = blockIdx.x * blockDim.x + threadIdx.x;
    if (n >= NTOK) return;
    #pragma unroll
    for (int k = 0; k < TOPK; ++k) {
        int e = idx[n*TOPK + k];
        int p = atomicAdd(&g_count[e], 1);
        g_list[e*CAP + p] = (n << 1) | k;
    }
}

__global__ void split3_kernel(const float* __restrict__ src, int n4, int which) {
    __nv_bfloat16* d = (which == 0) ? g_xl : (which == 1) ? g_uw : g_dw;
    size_t sz = (which == 0) ? (size_t)XSZ : (which == 1) ? (size_t)USZ : (size_t)DSZ;
    int i = blockIdx.x * blockDim.x + threadIdx.x;
    if (i >= n4) return;
    float4 v = ((const float4*)src)[i];
    float a[4] = {v.x, v.y, v.z, v.w};
    uint32_t u0[4], u1[4], u2[4];
    #pragma unroll
    for (int j = 0; j < 4; ++j) {
        __nv_bfloat16 b0 = __float2bfloat16(a[j]);
        float r1 = a[j] - __bfloat162float(b0);
        __nv_bfloat16 b1 = __float2bfloat16(r1);
        float r2 = r1 - __bfloat162float(b1);
        __nv_bfloat16 b2 = __float2bfloat16(r2);
        u0[j] = ((__nv_bfloat16_raw*)&b0)->x;
        u1[j] = ((__nv_bfloat16_raw*)&b1)->x;
        u2[j] = ((__nv_bfloat16_raw*)&b2)->x;
    }
    ((uint2*)(d       ))[i] = make_uint2(u0[0]|(u0[1]<<16), u0[2]|(u0[3]<<16));
    ((uint2*)(d +   sz))[i] = make_uint2(u1[0]|(u1[1]<<16), u1[2]|(u1[3]<<16));
    ((uint2*)(d + 2*sz))[i] = make_uint2(u2[0]|(u2[1]<<16), u2[2]|(u2[3]<<16));
}

// S=1: spikes = LIF(x@up^T) [3 A-limbs, combos i+j<=2]; S=2: out += w*LIF(spk@down^T)
template<int S>
__global__ __launch_bounds__(256, 1)
void gemm_lif(const float* __restrict__ ew, float* __restrict__ out) {
    constexpr int NA = (S == 1) ? 3 : 1;
    constexpr int NT = NA + 3;
    constexpr int KTOT = (S == 1) ? DD : EFF;
    constexpr size_t BSZ = (S == 1) ? (size_t)USZ : (size_t)DSZ;
    const int e = blockIdx.z, nc = blockIdx.y;
    const int cnt = g_count[e], start = blockIdx.x * MTOK;
    if (start >= cnt) return;

    extern __shared__ char dyn[];
    const uint32_t sb = s2u(dyn);
    __shared__ int s_ent[MTOK], s_ok[MTOK], s_rb[MR];
    __shared__ float s_w[MTOK];

    const int tid = threadIdx.x, lane = tid & 31, wid = tid >> 5;
    const int wm = wid & 1, wn = wid >> 1;
    if (tid < MTOK) {
        int i = start + tid, ok = (i < cnt) ? 1 : 0;
        int ent = g_list[e*CAP + (ok ? i : cnt - 1)];
        s_ent[tid] = ent; s_ok[tid] = ok; s_w[tid] = ew[ent];
    }
    __syncthreads();
    if (tid < MR) {
        int ent = s_ent[tid >> 2];
        s_rb[tid] = (S == 1) ? ((tid & 3)*NTOK + (ent >> 1))*DD
                             : ent*(TT*EFF) + (tid & 3)*EFF;
    }
    __syncthreads();

    const size_t wbase = (S == 1) ? ((size_t)e*EFF + (size_t)nc*128)*DD
                                  : ((size_t)e*DD  + (size_t)nc*128)*EFF;
    const __nv_bfloat16* Bp = (S == 1) ? g_uw : g_dw;

    float aH[4][4][4], aL[4][4][4];
    #pragma unroll
    for (int mi = 0; mi < 4; ++mi)
        #pragma unroll
        for (int nj = 0; nj < 4; ++nj)
            #pragma unroll
            for (int q = 0; q < 4; ++q) { aH[mi][nj][q] = 0.0f; aL[mi][nj][q] = 0.0f; }

    const uint32_t aoff = (uint32_t)((wm*64 + (lane & 15))*(SA*2) + (lane >> 4)*16);
    const uint32_t boff = (uint32_t)((wn*32 + (lane & 15))*(SA*2) + (lane >> 4)*16);

    for (int kc = 0; kc < KTOT/32; ++kc) {
        const int kb = kc * 32;
        __syncthreads();
        #pragma unroll
        for (int u = 0; u < NT*2; ++u) {
            int q = u*256 + tid;
            int tile = q >> 9, idx = q & 511, row = idx >> 2, seg = idx & 3;
            const __nv_bfloat16* src = (tile < NA)
                ? ((S == 1) ? g_xl + (size_t)tile*XSZ + s_rb[row] + kb + seg*8
                            : g_spk + (size_t)s_rb[row] + kb + seg*8)
                : Bp + (size_t)(tile - NA)*BSZ + wbase + (size_t)row*KTOT + kb + seg*8;
            *(uint4*)(dyn + tile*TILE_B + row*(SA*2) + seg*16) = *(const uint4*)src;
        }
        __syncthreads();
        #pragma unroll
        for (int k16 = 0; k16 < 2; ++k16) {
            const uint32_t ko = k16 * 32;
            uint32_t b[3][4][2];
            #pragma unroll
            for (int lb = 0; lb < 3; ++lb)
                #pragma unroll
                for (int g = 0; g < 2; ++g) {
                    uint32_t r0, r1, r2, r3;
                    LDSM4(r0, r1, r2, r3, sb + (NA+lb)*TILE_B + boff + g*16*(SA*2) + ko);
                    b[lb][g*2+0][0] = r0; b[lb][g*2+0][1] = r2;
                    b[lb][g*2+1][0] = r1; b[lb][g*2+1][1] = r3;
                }
            #pragma unroll
            for (int la = 0; la < NA; ++la) {
                uint32_t a[4][4];
                #pragma unroll
                for (int mi = 0; mi < 4; ++mi)
                    LDSM4(a[mi][0], a[mi][1], a[mi][2], a[mi][3],
                          sb + la*TILE_B + aoff + mi*16*(SA*2) + ko);
                #pragma unroll
                for (int lb = 0; lb < 3; ++lb) {
                    if (S == 1 && la + lb > 2) continue;   // keep i+j<=2
                    if (la == 0 && lb == 0) {
                        #pragma unroll
                        for (int mi = 0; mi < 4; ++mi)
                            #pragma unroll
                            for (int nj = 0; nj < 4; ++nj)
                                MMA(aH[mi][nj], a[mi], b[lb][nj]);
                    } else {
                        #pragma unroll
                        for (int mi = 0; mi < 4; ++mi)
                            #pragma unroll
                            for (int nj = 0; nj < 4; ++nj)
                                MMA(aL[mi][nj], a[mi], b[lb][nj]);
                    }
                }
            }
        }
    }
    __syncthreads();

    float* ep = (float*)dyn;
    #pragma unroll
    for (int mi = 0; mi < 4; ++mi)
        #pragma unroll
        for (int nj = 0; nj < 4; ++nj) {
            int R = wm*64 + mi*16 + (lane >> 2);
            int C = wn*32 + nj*8 + (lane & 3)*2;
            *(float2*)&ep[R*EPS + C] = make_float2(aH[mi][nj][0] + aL[mi][nj][0],
                                                   aH[mi][nj][1] + aL[mi][nj][1]);
            *(float2*)&ep[(R+8)*EPS + C] = make_float2(aH[mi][nj][2] + aL[mi][nj][2],
                                                       aH[mi][nj][3] + aL[mi][nj][3]);
        }
    __syncthreads();
    #pragma unroll
    for (int i = 0; i < 8; ++i) {
        int c = i*256 + tid;
        int sl = c >> 6, cp = c & 63;
        if (!s_ok[sl]) continue;
        float2 v0 = *(float2*)&ep[(sl*4+0)*EPS + cp*2];
        float2 v1 = *(float2*)&ep[(sl*4+1)*EPS + cp*2];
        float2 v2 = *(float2*)&ep[(sl*4+2)*EPS + cp*2];
        float2 v3 = *(float2*)&ep[(sl*4+3)*EPS + cp*2];
        float a0,a1,a2,a3, b0,b1,b2,b3;
        lif4(v0.x, v1.x, v2.x, v3.x, a0, a1, a2, a3);
        lif4(v0.y, v1.y, v2.y, v3.y, b0, b1, b2, b3);
        if (S == 1) {
            __nv_bfloat16* spb = g_spk + (size_t)s_ent[sl]*(TT*EFF) + nc*128 + cp*2;
            uint32_t p0 = (a0 != 0.0f ? 0x3F80u : 0u) | (b0 != 0.0f ? 0x3F800000u : 0u);
            uint32_t p1 = (a1 != 0.0f ? 0x3F80u : 0u) | (b1 != 0.0f ? 0x3F800000u : 0u);
            uint32_t p2 = (a2 != 0.0f ? 0x3F80u : 0u) | (b2 != 0.0f ? 0x3F800000u : 0u);
            uint32_t p3 = (a3 != 0.0f ? 0x3F80u : 0u) | (b3 != 0.0f ? 0x3F800000u : 0u);
            *(uint32_t*)(spb + 0*EFF) = p0;
            *(uint32_t*)(spb + 1*EFF) = p1;
            *(uint32_t*)(spb + 2*EFF) = p2;
            *(uint32_t*)(spb + 3*EFF) = p3;
        } else {
            int n = s_ent[sl] >> 1;
            float w = s_w[sl];
            float s[4][2] = {{a0,b0},{a1,b1},{a2,b2},{a3,b3}};
            #pragma unroll
            for (int t = 0; t < 4; ++t) {
                float* ob = out + ((size_t)t*NTOK + n)*DD + nc*128 + cp*2;
                if (s[t][0] != 0.0f) atomicAdd(ob,     w);
                if (s[t][1] != 0.0f) atomicAdd(ob + 1, w);
            }
        }
    }
}

extern "C" void kernel_launch(void* const* d_in, const int* in_sizes, int n_in,
                              void* d_out, int out_size) {
    const float* x  = (const float*)d_in[0];
    const int*   ei = (const int*)  d_in[1];
    const float* ew = (const float*)d_in[2];
    const float* up = (const float*)d_in[3];
    const float* dw = (const float*)d_in[4];
    float* out = (float*)d_out;
    (void)in_sizes; (void)n_in;

    cudaFuncSetAttribute(gemm_lif<1>, cudaFuncAttributeMaxDynamicSharedMemorySize, SMB);
    cudaFuncSetAttribute(gemm_lif<2>, cudaFuncAttributeMaxDynamicSharedMemorySize, SMB);

    cudaMemsetAsync(d_out, 0, (size_t)out_size * sizeof(float), 0);
    reset_kernel<<<1, 32>>>();
    route_kernel<<<NTOK/256, 256>>>(ei);
    split3_kernel<<<(XSZ/4 + 255)/256, 256>>>(x,  XSZ/4, 0);
    split3_kernel<<<(USZ/4 + 255)/256, 256>>>(up, USZ/4, 1);
    split3_kernel<<<(DSZ/4 + 255)/256, 256>>>(dw, DSZ/4, 2);
    gemm_lif<1><<<dim3(CAP/MTOK, EFF/128, EE), 256, SMB>>>(ew, out);
    gemm_lif<2><<<dim3(CAP/MTOK, DD/128,  EE), 256, SMB>>>(ew, out);
}

// round 10
// speedup vs baseline: 1.7156x; 1.2555x over previous
#include <cuda_runtime.h>
#include <cuda_bf16.h>
#include <cstdint>

#define TT 4
#define NTOK 8192
#define DD 1024
#define EE 8
#define EFF 512
#define TOPK 2
#define CAP (NTOK*TOPK)
#define MTOK 32
#define MR 128
#define SA 40
#define TILE_B (MR*SA*2)
#define XSZ (TT*NTOK*DD)
#define USZ (EE*EFF*DD)
#define DSZ (EE*DD*EFF)
#define EPS 132

__device__ int g_count[EE];
__device__ int g_list[EE*CAP];
__device__ __nv_bfloat16 g_xl[(size_t)3*XSZ];
__device__ __nv_bfloat16 g_uw[(size_t)3*USZ];
__device__ __nv_bfloat16 g_dw[(size_t)3*DSZ];
__device__ __nv_bfloat16 g_spk[(size_t)CAP*TT*EFF];

static __device__ __forceinline__ uint32_t s2u(const void* p) {
    uint32_t a;
    asm("{ .reg .u64 t; cvta.to.shared.u64 t, %1; cvt.u32.u64 %0, t; }" : "=r"(a) : "l"(p));
    return a;
}
#define CP16(dst, src) asm volatile("cp.async.cg.shared.global [%0], [%1], 16;" \
    :: "r"(dst), "l"(src) : "memory")
#define CPCOMMIT() asm volatile("cp.async.commit_group;" ::: "memory")
#define CPWAIT(n)  asm volatile("cp.async.wait_group %0;" :: "n"(n) : "memory")
#define LDSM4(r0,r1,r2,r3,addr) asm volatile( \
    "ldmatrix.sync.aligned.m8n8.x4.shared.b16 {%0,%1,%2,%3}, [%4];" \
    : "=r"(r0),"=r"(r1),"=r"(r2),"=r"(r3) : "r"(addr))
#define MMA(c, a, b) asm volatile( \
    "mma.sync.aligned.m16n8k16.row.col.f32.bf16.bf16.f32 " \
    "{%0,%1,%2,%3},{%4,%5,%6,%7},{%8,%9},{%0,%1,%2,%3};" \
    : "+f"((c)[0]),"+f"((c)[1]),"+f"((c)[2]),"+f"((c)[3]) \
    : "r"((a)[0]),"r"((a)[1]),"r"((a)[2]),"r"((a)[3]), "r"((b)[0]),"r"((b)[1]))

static __device__ __forceinline__ void lif4(float v0, float v1, float v2, float v3,
                                            float &s0, float &s1, float &s2, float &s3) {
    float m = v0;     s0 = (m > 1.0f) ? 1.0f : 0.0f; m -= s0;
    m = 0.9f*m + v1;  s1 = (m > 1.0f) ? 1.0f : 0.0f; m -= s1;
    m = 0.9f*m + v2;  s2 = (m > 1.0f) ? 1.0f : 0.0f; m -= s2;
    m = 0.9f*m + v3;  s3 = (m > 1.0f) ? 1.0f : 0.0f;
}

__global__ void reset_kernel() { if (threadIdx.x < EE) g_count[threadIdx.x] = 0; }

__global__ void route_kernel(const int* __restrict__ idx) {
    int n = blockIdx.x * blockDim.x + threadIdx.x;
    if (n >= NTOK) return;
    #pragma unroll
    for (int k = 0; k < TOPK; ++k) {
        int e = idx[n*TOPK + k];
        int p = atomicAdd(&g_count[e], 1);
        g_list[e*CAP + p] = (n << 1) | k;
    }
}

__global__ void split3_kernel(const float* __restrict__ src, int n4, int which) {
    __nv_bfloat16* d = (which == 0) ? g_xl : (which == 1) ? g_uw : g_dw;
    size_t sz = (which == 0) ? (size_t)XSZ : (which == 1) ? (size_t)USZ : (size_t)DSZ;
    int i = blockIdx.x * blockDim.x + threadIdx.x;
    if (i >= n4) return;
    float4 v = ((const float4*)src)[i];
    float a[4] = {v.x, v.y, v.z, v.w};
    uint32_t u0[4], u1[4], u2[4];
    #pragma unroll
    for (int j = 0; j < 4; ++j) {
        __nv_bfloat16 b0 = __float2bfloat16(a[j]);
        float r1 = a[j] - __bfloat162float(b0);
        __nv_bfloat16 b1 = __float2bfloat16(r1);
        float r2 = r1 - __bfloat162float(b1);
        __nv_bfloat16 b2 = __float2bfloat16(r2);
        u0[j] = ((__nv_bfloat16_raw*)&b0)->x;
        u1[j] = ((__nv_bfloat16_raw*)&b1)->x;
        u2[j] = ((__nv_bfloat16_raw*)&b2)->x;
    }
    ((uint2*)(d       ))[i] = make_uint2(u0[0]|(u0[1]<<16), u0[2]|(u0[3]<<16));
    ((uint2*)(d +   sz))[i] = make_uint2(u1[0]|(u1[1]<<16), u1[2]|(u1[3]<<16));
    ((uint2*)(d + 2*sz))[i] = make_uint2(u2[0]|(u2[1]<<16), u2[2]|(u2[3]<<16));
}

// S=1: spikes = LIF(x@up^T) [3 A-limbs, combos i+j<=2]; S=2: out += w*LIF(spk@down^T)
template<int S>
__global__ __launch_bounds__(256, 1)
void gemm_lif(const float* __restrict__ ew, float* __restrict__ out) {
    constexpr int NA = (S == 1) ? 3 : 1;
    constexpr int NT = NA + 3;
    constexpr int KTOT = (S == 1) ? DD : EFF;
    constexpr size_t BSZ = (S == 1) ? (size_t)USZ : (size_t)DSZ;
    constexpr int BUF = NT * TILE_B;
    const int e = blockIdx.z, nc = blockIdx.y;
    const int cnt = g_count[e], start = blockIdx.x * MTOK;
    if (start >= cnt) return;

    extern __shared__ char dyn[];
    const uint32_t sb = s2u(dyn);
    __shared__ int s_ent[MTOK], s_ok[MTOK], s_rb[MR];
    __shared__ float s_w[MTOK];

    const int tid = threadIdx.x, lane = tid & 31, wid = tid >> 5;
    const int wm = wid & 1, wn = wid >> 1;
    if (tid < MTOK) {
        int i = start + tid, ok = (i < cnt) ? 1 : 0;
        int ent = g_list[e*CAP + (ok ? i : cnt - 1)];
        s_ent[tid] = ent; s_ok[tid] = ok; s_w[tid] = ew[ent];
    }
    __syncthreads();
    if (tid < MR) {
        int ent = s_ent[tid >> 2];
        s_rb[tid] = (S == 1) ? ((tid & 3)*NTOK + (ent >> 1))*DD
                             : ent*(TT*EFF) + (tid & 3)*EFF;
    }
    __syncthreads();

    const size_t wbase = (S == 1) ? ((size_t)e*EFF + (size_t)nc*128)*DD
                                  : ((size_t)e*DD  + (size_t)nc*128)*EFF;
    const __nv_bfloat16* Bp = (S == 1) ? g_uw : g_dw;

    float aH[4][4][4], aL[4][4][4];
    #pragma unroll
    for (int mi = 0; mi < 4; ++mi)
        #pragma unroll
        for (int nj = 0; nj < 4; ++nj)
            #pragma unroll
            for (int q = 0; q < 4; ++q) { aH[mi][nj][q] = 0.0f; aL[mi][nj][q] = 0.0f; }

    const uint32_t aoff = (uint32_t)((wm*64 + (lane & 15))*(SA*2) + (lane >> 4)*16);
    const uint32_t boff = (uint32_t)((wn*32 + (lane & 15))*(SA*2) + (lane >> 4)*16);

    // staging: thread tid covers (tile, row, seg); cp.async 16B each
    const int stile = tid >> 9 ;  // unused placeholder (kept simple below)

    // ---- prologue: stage chunk 0 into buffer 0 ----
    #pragma unroll
    for (int u = 0; u < NT*2; ++u) {
        int q = u*256 + tid;
        int tile = q >> 9, idx = q & 511, row = idx >> 2, seg = idx & 3;
        const __nv_bfloat16* src = (tile < NA)
            ? ((S == 1) ? g_xl + (size_t)tile*XSZ + s_rb[row] + seg*8
                        : g_spk + (size_t)s_rb[row] + seg*8)
            : Bp + (size_t)(tile - NA)*BSZ + wbase + (size_t)row*KTOT + seg*8;
        CP16(sb + tile*TILE_B + row*(SA*2) + seg*16, src);
    }
    CPCOMMIT();

    for (int kc = 0; kc < KTOT/32; ++kc) {
        if (kc + 1 < KTOT/32) {
            const int kb = (kc + 1) * 32;
            const uint32_t dstb = sb + ((kc + 1) & 1) * BUF;
            #pragma unroll
            for (int u = 0; u < NT*2; ++u) {
                int q = u*256 + tid;
                int tile = q >> 9, idx = q & 511, row = idx >> 2, seg = idx & 3;
                const __nv_bfloat16* src = (tile < NA)
                    ? ((S == 1) ? g_xl + (size_t)tile*XSZ + s_rb[row] + kb + seg*8
                                : g_spk + (size_t)s_rb[row] + kb + seg*8)
                    : Bp + (size_t)(tile - NA)*BSZ + wbase + (size_t)row*KTOT + kb + seg*8;
                CP16(dstb + tile*TILE_B + row*(SA*2) + seg*16, src);
            }
            CPCOMMIT();
            CPWAIT(1);          // chunk kc landed; chunk kc+1 in flight
        } else {
            CPWAIT(0);
        }
        __syncthreads();
        const uint32_t base = sb + (kc & 1) * BUF;
        #pragma unroll
        for (int k16 = 0; k16 < 2; ++k16) {
            const uint32_t ko = k16 * 32;
            uint32_t b[3][4][2];
            #pragma unroll
            for (int lb = 0; lb < 3; ++lb)
                #pragma unroll
                for (int g = 0; g < 2; ++g) {
                    uint32_t r0, r1, r2, r3;
                    LDSM4(r0, r1, r2, r3, base + (NA+lb)*TILE_B + boff + g*16*(SA*2) + ko);
                    b[lb][g*2+0][0] = r0; b[lb][g*2+0][1] = r2;
                    b[lb][g*2+1][0] = r1; b[lb][g*2+1][1] = r3;
                }
            #pragma unroll
            for (int la = 0; la < NA; ++la) {
                uint32_t a[4][4];
                #pragma unroll
                for (int mi = 0; mi < 4; ++mi)
                    LDSM4(a[mi][0], a[mi][1], a[mi][2], a[mi][3],
                          base + la*TILE_B + aoff + mi*16*(SA*2) + ko);
                #pragma unroll
                for (int lb = 0; lb < 3; ++lb) {
                    if (S == 1 && la + lb > 2) continue;   // keep i+j<=2
                    if (la == 0 && lb == 0) {
                        #pragma unroll
                        for (int mi = 0; mi < 4; ++mi)
                            #pragma unroll
                            for (int nj = 0; nj < 4; ++nj)
                                MMA(aH[mi][nj], a[mi], b[lb][nj]);
                    } else {
                        #pragma unroll
                        for (int mi = 0; mi < 4; ++mi)
                            #pragma unroll
                            for (int nj = 0; nj < 4; ++nj)
                                MMA(aL[mi][nj], a[mi], b[lb][nj]);
                    }
                }
            }
        }
        __syncthreads();   // compute done before buffer (kc&1) is restaged at kc+1
    }

    float* ep = (float*)dyn;
    #pragma unroll
    for (int mi = 0; mi < 4; ++mi)
        #pragma unroll
        for (int nj = 0; nj < 4; ++nj) {
            int R = wm*64 + mi*16 + (lane >> 2);
            int C = wn*32 + nj*8 + (lane & 3)*2;
            *(float2*)&ep[R*EPS + C] = make_float2(aH[mi][nj][0] + aL[mi][nj][0],
                                                   aH[mi][nj][1] + aL[mi][nj][1]);
            *(float2*)&ep[(R+8)*EPS + C] = make_float2(aH[mi][nj][2] + aL[mi][nj][2],
                                                       aH[mi][nj][3] + aL[mi][nj][3]);
        }
    __syncthreads();
    #pragma unroll
    for (int i = 0; i < 8; ++i) {
        int c = i*256 + tid;
        int sl = c >> 6, cp = c & 63;
        if (!s_ok[sl]) continue;
        float2 v0 = *(float2*)&ep[(sl*4+0)*EPS + cp*2];
        float2 v1 = *(float2*)&ep[(sl*4+1)*EPS + cp*2];
        float2 v2 = *(float2*)&ep[(sl*4+2)*EPS + cp*2];
        float2 v3 = *(float2*)&ep[(sl*4+3)*EPS + cp*2];
        float a0,a1,a2,a3, b0,b1,b2,b3;
        lif4(v0.x, v1.x, v2.x, v3.x, a0, a1, a2, a3);
        lif4(v0.y, v1.y, v2.y, v3.y, b0, b1, b2, b3);
        if (S == 1) {
            __nv_bfloat16* spb = g_spk + (size_t)s_ent[sl]*(TT*EFF) + nc*128 + cp*2;
            uint32_t p0 = (a0 != 0.0f ? 0x3F80u : 0u) | (b0 != 0.0f ? 0x3F800000u : 0u);
            uint32_t p1 = (a1 != 0.0f ? 0x3F80u : 0u) | (b1 != 0.0f ? 0x3F800000u : 0u);
            uint32_t p2 = (a2 != 0.0f ? 0x3F80u : 0u) | (b2 != 0.0f ? 0x3F800000u : 0u);
            uint32_t p3 = (a3 != 0.0f ? 0x3F80u : 0u) | (b3 != 0.0f ? 0x3F800000u : 0u);
            *(uint32_t*)(spb + 0*EFF) = p0;
            *(uint32_t*)(spb + 1*EFF) = p1;
            *(uint32_t*)(spb + 2*EFF) = p2;
            *(uint32_t*)(spb + 3*EFF) = p3;
        } else {
            int n = s_ent[sl] >> 1;
            float w = s_w[sl];
            float s[4][2] = {{a0,b0},{a1,b1},{a2,b2},{a3,b3}};
            #pragma unroll
            for (int t = 0; t < 4; ++t) {
                float* ob = out + ((size_t)t*NTOK + n)*DD + nc*128 + cp*2;
                if (s[t][0] != 0.0f) atomicAdd(ob,     w);
                if (s[t][1] != 0.0f) atomicAdd(ob + 1, w);
            }
        }
    }
}

#define S1_SMEM (2*6*TILE_B)   // 122880 (>= epilogue 67584)
#define S2_SMEM (2*4*TILE_B)   // 81920

extern "C" void kernel_launch(void* const* d_in, const int* in_sizes, int n_in,
                              void* d_out, int out_size) {
    const float* x  = (const float*)d_in[0];
    const int*   ei = (const int*)  d_in[1];
    const float* ew = (const float*)d_in[2];
    const float* up = (const float*)d_in[3];
    const float* dw = (const float*)d_in[4];
    float* out = (float*)d_out;
    (void)in_sizes; (void)n_in;

    cudaFuncSetAttribute(gemm_lif<1>, cudaFuncAttributeMaxDynamicSharedMemorySize, S1_SMEM);
    cudaFuncSetAttribute(gemm_lif<2>, cudaFuncAttributeMaxDynamicSharedMemorySize, S2_SMEM);

    cudaMemsetAsync(d_out, 0, (size_t)out_size * sizeof(float), 0);
    reset_kernel<<<1, 32>>>();
    route_kernel<<<NTOK/256, 256>>>(ei);
    split3_kernel<<<(XSZ/4 + 255)/256, 256>>>(x,  XSZ/4, 0);
    split3_kernel<<<(USZ/4 + 255)/256, 256>>>(up, USZ/4, 1);
    split3_kernel<<<(DSZ/4 + 255)/256, 256>>>(dw, DSZ/4, 2);
    gemm_lif<1><<<dim3(CAP/MTOK, EFF/128, EE), 256, S1_SMEM>>>(ew, out);
    gemm_lif<2><<<dim3(CAP/MTOK, DD/128,  EE), 256, S2_SMEM>>>(ew, out);
}

// round 11
// speedup vs baseline: 2.2876x; 1.3335x over previous
#include <cuda_runtime.h>
#include <cuda_fp16.h>
#include <cstdint>

#define TT 4
#define NTOK 8192
#define DD 1024
#define EE 8
#define EFF 512
#define TOPK 2
#define CAP (NTOK*TOPK)
#define MTOK 32
#define MR 128
#define SA 40
#define TILE_B (MR*SA*2)
#define XSZ (TT*NTOK*DD)
#define USZ (EE*EFF*DD)
#define DSZ (EE*DD*EFF)
#define EPS 132
#define RSC (1.0f/2048.0f)

__device__ int g_count[EE];
__device__ int g_list[EE*CAP];
__device__ __half g_xl[(size_t)3*XSZ];   // x0, x1s(<<11), x1u
__device__ __half g_uw[(size_t)2*USZ];   // u0, u1s
__device__ __half g_dw[(size_t)2*DSZ];   // d0, d1s
__device__ __half g_spk[(size_t)CAP*TT*EFF];

static __device__ __forceinline__ uint32_t s2u(const void* p) {
    uint32_t a;
    asm("{ .reg .u64 t; cvta.to.shared.u64 t, %1; cvt.u32.u64 %0, t; }" : "=r"(a) : "l"(p));
    return a;
}
#define CP16(dst, src) asm volatile("cp.async.cg.shared.global [%0], [%1], 16;" \
    :: "r"(dst), "l"(src) : "memory")
#define CPCOMMIT() asm volatile("cp.async.commit_group;" ::: "memory")
#define CPWAIT(n)  asm volatile("cp.async.wait_group %0;" :: "n"(n) : "memory")
#define LDSM4(r0,r1,r2,r3,addr) asm volatile( \
    "ldmatrix.sync.aligned.m8n8.x4.shared.b16 {%0,%1,%2,%3}, [%4];" \
    : "=r"(r0),"=r"(r1),"=r"(r2),"=r"(r3) : "r"(addr))
#define MMA(c, a, b) asm volatile( \
    "mma.sync.aligned.m16n8k16.row.col.f32.f16.f16.f32 " \
    "{%0,%1,%2,%3},{%4,%5,%6,%7},{%8,%9},{%0,%1,%2,%3};" \
    : "+f"((c)[0]),"+f"((c)[1]),"+f"((c)[2]),"+f"((c)[3]) \
    : "r"((a)[0]),"r"((a)[1]),"r"((a)[2]),"r"((a)[3]), "r"((b)[0]),"r"((b)[1]))

static __device__ __forceinline__ void lif4(float v0, float v1, float v2, float v3,
                                            float &s0, float &s1, float &s2, float &s3) {
    float m = v0;     s0 = (m > 1.0f) ? 1.0f : 0.0f; m -= s0;
    m = 0.9f*m + v1;  s1 = (m > 1.0f) ? 1.0f : 0.0f; m -= s1;
    m = 0.9f*m + v2;  s2 = (m > 1.0f) ? 1.0f : 0.0f; m -= s2;
    m = 0.9f*m + v3;  s3 = (m > 1.0f) ? 1.0f : 0.0f;
}

__global__ void reset_kernel() { if (threadIdx.x < EE) g_count[threadIdx.x] = 0; }

__global__ void route_kernel(const int* __restrict__ idx) {
    int n = blockIdx.x * blockDim.x + threadIdx.x;
    if (n >= NTOK) return;
    #pragma unroll
    for (int k = 0; k < TOPK; ++k) {
        int e = idx[n*TOPK + k];
        int p = atomicAdd(&g_count[e], 1);
        g_list[e*CAP + p] = (n << 1) | k;
    }
}

static __device__ __forceinline__ uint32_t hbits(__half h) {
    return (uint32_t)__half_as_ushort(h);
}

// which: 0 = x (3 planes), 1 = up (2 planes), 2 = down (2 planes)
__global__ void split_kernel(const float* __restrict__ src, int n4, int which) {
    __half* d = (which == 0) ? g_xl : (which == 1) ? g_uw : g_dw;
    size_t sz = (which == 0) ? (size_t)XSZ : (which == 1) ? (size_t)USZ : (size_t)DSZ;
    int i = blockIdx.x * blockDim.x + threadIdx.x;
    if (i >= n4) return;
    float4 v = ((const float4*)src)[i];
    float a[4] = {v.x, v.y, v.z, v.w};
    uint32_t u0[4], u1[4], u2[4];
    #pragma unroll
    for (int j = 0; j < 4; ++j) {
        __half h0 = __float2half_rn(a[j]);
        float r = a[j] - __half2float(h0);
        __half h1s = __float2half_rn(r * 2048.0f);
        u0[j] = hbits(h0);
        u1[j] = hbits(h1s);
        u2[j] = hbits(__float2half_rn(r));
    }
    ((uint2*)(d       ))[i] = make_uint2(u0[0]|(u0[1]<<16), u0[2]|(u0[3]<<16));
    ((uint2*)(d +   sz))[i] = make_uint2(u1[0]|(u1[1]<<16), u1[2]|(u1[3]<<16));
    if (which == 0)
        ((uint2*)(d + 2*sz))[i] = make_uint2(u2[0]|(u2[1]<<16), u2[2]|(u2[3]<<16));
}

// S=1: spikes = LIF(x@up^T); A tiles {x0,x1s,x1u}, B tiles {u0,u1s}
//      combos: (x0,u0)->H; (x0,u1s),(x1s,u0),(x1u,u1s)->L.  val = H + L/2048
// S=2: out += w*LIF(spk@down^T); A {spk}, B {d0,d1s}: (s,d0)->H; (s,d1s)->L
template<int S>
__global__ __launch_bounds__(256, 1)
void gemm_lif(const float* __restrict__ ew, float* __restrict__ out) {
    constexpr int NA = (S == 1) ? 3 : 1;
    constexpr int NT = NA + 2;
    constexpr int KTOT = (S == 1) ? DD : EFF;
    constexpr size_t BSZ = (S == 1) ? (size_t)USZ : (size_t)DSZ;
    constexpr int BUF = NT * TILE_B;
    const int e = blockIdx.z, nc = blockIdx.y;
    const int cnt = g_count[e], start = blockIdx.x * MTOK;
    if (start >= cnt) return;

    extern __shared__ char dyn[];
    const uint32_t sb = s2u(dyn);
    __shared__ int s_ent[MTOK], s_ok[MTOK], s_rb[MR];
    __shared__ float s_w[MTOK];

    const int tid = threadIdx.x, lane = tid & 31, wid = tid >> 5;
    const int wm = wid & 1, wn = wid >> 1;
    if (tid < MTOK) {
        int i = start + tid, ok = (i < cnt) ? 1 : 0;
        int ent = g_list[e*CAP + (ok ? i : cnt - 1)];
        s_ent[tid] = ent; s_ok[tid] = ok; s_w[tid] = ew[ent];
    }
    __syncthreads();
    if (tid < MR) {
        int ent = s_ent[tid >> 2];
        s_rb[tid] = (S == 1) ? ((tid & 3)*NTOK + (ent >> 1))*DD
                             : ent*(TT*EFF) + (tid & 3)*EFF;
    }
    __syncthreads();

    const size_t wbase = (S == 1) ? ((size_t)e*EFF + (size_t)nc*128)*DD
                                  : ((size_t)e*DD  + (size_t)nc*128)*EFF;
    const __half* Bp = (S == 1) ? g_uw : g_dw;

    float aH[4][4][4], aL[4][4][4];
    #pragma unroll
    for (int mi = 0; mi < 4; ++mi)
        #pragma unroll
        for (int nj = 0; nj < 4; ++nj)
            #pragma unroll
            for (int q = 0; q < 4; ++q) { aH[mi][nj][q] = 0.0f; aL[mi][nj][q] = 0.0f; }

    const uint32_t aoff = (uint32_t)((wm*64 + (lane & 15))*(SA*2) + (lane >> 4)*16);
    const uint32_t boff = (uint32_t)((wn*32 + (lane & 15))*(SA*2) + (lane >> 4)*16);

    // ---- prologue: stage chunk 0 into buffer 0 ----
    #pragma unroll
    for (int u = 0; u < NT*2; ++u) {
        int q = u*256 + tid;
        int tile = q >> 9, idx = q & 511, row = idx >> 2, seg = idx & 3;
        const __half* src = (tile < NA)
            ? ((S == 1) ? g_xl + (size_t)tile*XSZ + s_rb[row] + seg*8
                        : g_spk + (size_t)s_rb[row] + seg*8)
            : Bp + (size_t)(tile - NA)*BSZ + wbase + (size_t)row*KTOT + seg*8;
        CP16(sb + tile*TILE_B + row*(SA*2) + seg*16, src);
    }
    CPCOMMIT();

    for (int kc = 0; kc < KTOT/32; ++kc) {
        if (kc + 1 < KTOT/32) {
            const int kb = (kc + 1) * 32;
            const uint32_t dstb = sb + ((kc + 1) & 1) * BUF;
            #pragma unroll
            for (int u = 0; u < NT*2; ++u) {
                int q = u*256 + tid;
                int tile = q >> 9, idx = q & 511, row = idx >> 2, seg = idx & 3;
                const __half* src = (tile < NA)
                    ? ((S == 1) ? g_xl + (size_t)tile*XSZ + s_rb[row] + kb + seg*8
                                : g_spk + (size_t)s_rb[row] + kb + seg*8)
                    : Bp + (size_t)(tile - NA)*BSZ + wbase + (size_t)row*KTOT + kb + seg*8;
                CP16(dstb + tile*TILE_B + row*(SA*2) + seg*16, src);
            }
            CPCOMMIT();
            CPWAIT(1);
        } else {
            CPWAIT(0);
        }
        __syncthreads();
        const uint32_t base = sb + (kc & 1) * BUF;
        #pragma unroll
        for (int k16 = 0; k16 < 2; ++k16) {
            const uint32_t ko = k16 * 32;
            uint32_t b[2][4][2];
            #pragma unroll
            for (int lb = 0; lb < 2; ++lb)
                #pragma unroll
                for (int g = 0; g < 2; ++g) {
                    uint32_t r0, r1, r2, r3;
                    LDSM4(r0, r1, r2, r3, base + (NA+lb)*TILE_B + boff + g*16*(SA*2) + ko);
                    b[lb][g*2+0][0] = r0; b[lb][g*2+0][1] = r2;
                    b[lb][g*2+1][0] = r1; b[lb][g*2+1][1] = r3;
                }
            #pragma unroll
            for (int la = 0; la < NA; ++la) {
                uint32_t a[4][4];
                #pragma unroll
                for (int mi = 0; mi < 4; ++mi)
                    LDSM4(a[mi][0], a[mi][1], a[mi][2], a[mi][3],
                          base + la*TILE_B + aoff + mi*16*(SA*2) + ko);
                if (la == 0) {
                    #pragma unroll
                    for (int mi = 0; mi < 4; ++mi)
                        #pragma unroll
                        for (int nj = 0; nj < 4; ++nj)
                            MMA(aH[mi][nj], a[mi], b[0][nj]);     // (0,0) -> H
                    #pragma unroll
                    for (int mi = 0; mi < 4; ++mi)
                        #pragma unroll
                        for (int nj = 0; nj < 4; ++nj)
                            MMA(aL[mi][nj], a[mi], b[1][nj]);     // (0,1s) -> L
                } else if (la == 1) {
                    #pragma unroll
                    for (int mi = 0; mi < 4; ++mi)
                        #pragma unroll
                        for (int nj = 0; nj < 4; ++nj)
                            MMA(aL[mi][nj], a[mi], b[0][nj]);     // (1s,0) -> L
                } else {
                    #pragma unroll
                    for (int mi = 0; mi < 4; ++mi)
                        #pragma unroll
                        for (int nj = 0; nj < 4; ++nj)
                            MMA(aL[mi][nj], a[mi], b[1][nj]);     // (1u,1s) -> L
                }
            }
        }
        __syncthreads();
    }

    float* ep = (float*)dyn;
    #pragma unroll
    for (int mi = 0; mi < 4; ++mi)
        #pragma unroll
        for (int nj = 0; nj < 4; ++nj) {
            int R = wm*64 + mi*16 + (lane >> 2);
            int C = wn*32 + nj*8 + (lane & 3)*2;
            *(float2*)&ep[R*EPS + C] = make_float2(aH[mi][nj][0] + aL[mi][nj][0]*RSC,
                                                   aH[mi][nj][1] + aL[mi][nj][1]*RSC);
            *(float2*)&ep[(R+8)*EPS + C] = make_float2(aH[mi][nj][2] + aL[mi][nj][2]*RSC,
                                                       aH[mi][nj][3] + aL[mi][nj][3]*RSC);
        }
    __syncthreads();
    #pragma unroll
    for (int i = 0; i < 8; ++i) {
        int c = i*256 + tid;
        int sl = c >> 6, cp = c & 63;
        if (!s_ok[sl]) continue;
        float2 v0 = *(float2*)&ep[(sl*4+0)*EPS + cp*2];
        float2 v1 = *(float2*)&ep[(sl*4+1)*EPS + cp*2];
        float2 v2 = *(float2*)&ep[(sl*4+2)*EPS + cp*2];
        float2 v3 = *(float2*)&ep[(sl*4+3)*EPS + cp*2];
        float a0,a1,a2,a3, b0,b1,b2,b3;
        lif4(v0.x, v1.x, v2.x, v3.x, a0, a1, a2, a3);
        lif4(v0.y, v1.y, v2.y, v3.y, b0, b1, b2, b3);
        if (S == 1) {
            __half* spb = g_spk + (size_t)s_ent[sl]*(TT*EFF) + nc*128 + cp*2;
            uint32_t p0 = (a0 != 0.0f ? 0x3C00u : 0u) | (b0 != 0.0f ? 0x3C000000u : 0u);
            uint32_t p1 = (a1 != 0.0f ? 0x3C00u : 0u) | (b1 != 0.0f ? 0x3C000000u : 0u);
            uint32_t p2 = (a2 != 0.0f ? 0x3C00u : 0u) | (b2 != 0.0f ? 0x3C000000u : 0u);
            uint32_t p3 = (a3 != 0.0f ? 0x3C00u : 0u) | (b3 != 0.0f ? 0x3C000000u : 0u);
            *(uint32_t*)(spb + 0*EFF) = p0;
            *(uint32_t*)(spb + 1*EFF) = p1;
            *(uint32_t*)(spb + 2*EFF) = p2;
            *(uint32_t*)(spb + 3*EFF) = p3;
        } else {
            int n = s_ent[sl] >> 1;
            float w = s_w[sl];
            float s[4][2] = {{a0,b0},{a1,b1},{a2,b2},{a3,b3}};
            #pragma unroll
            for (int t = 0; t < 4; ++t) {
                float* ob = out + ((size_t)t*NTOK + n)*DD + nc*128 + cp*2;
                if (s[t][0] != 0.0f) atomicAdd(ob,     w);
                if (s[t][1] != 0.0f) atomicAdd(ob + 1, w);
            }
        }
    }
}

#define S1_SMEM (2*5*TILE_B)                       // 102400 >= epilogue 67584
#define S2_SMEM 69632                              // >= max(2*3*TILE_B=61440, 67584)

extern "C" void kernel_launch(void* const* d_in, const int* in_sizes, int n_in,
                              void* d_out, int out_size) {
    const float* x  = (const float*)d_in[0];
    const int*   ei = (const int*)  d_in[1];
    const float* ew = (const float*)d_in[2];
    const float* up = (const float*)d_in[3];
    const float* dw = (const float*)d_in[4];
    float* out = (float*)d_out;
    (void)in_sizes; (void)n_in;

    cudaFuncSetAttribute(gemm_lif<1>, cudaFuncAttributeMaxDynamicSharedMemorySize, S1_SMEM);
    cudaFuncSetAttribute(gemm_lif<2>, cudaFuncAttributeMaxDynamicSharedMemorySize, S2_SMEM);

    cudaMemsetAsync(d_out, 0, (size_t)out_size * sizeof(float), 0);
    reset_kernel<<<1, 32>>>();
    route_kernel<<<NTOK/256, 256>>>(ei);
    split_kernel<<<(XSZ/4 + 255)/256, 256>>>(x,  XSZ/4, 0);
    split_kernel<<<(USZ/4 + 255)/256, 256>>>(up, USZ/4, 1);
    split_kernel<<<(DSZ/4 + 255)/256, 256>>>(dw, DSZ/4, 2);
    gemm_lif<1><<<dim3(CAP/MTOK, EFF/128, EE), 256, S1_SMEM>>>(ew, out);
    gemm_lif<2><<<dim3(CAP/MTOK, DD/128,  EE), 256, S2_SMEM>>>(ew, out);
}

// round 12
// speedup vs baseline: 2.6183x; 1.1445x over previous
#include <cuda_runtime.h>
#include <cuda_fp16.h>
#include <cstdint>

#define TT 4
#define NTOK 8192
#define DD 1024
#define EE 8
#define EFF 512
#define TOPK 2
#define CAP (NTOK*TOPK)
#define MTOK 32
#define MR 128
#define SA 40
#define TILE_B (MR*SA*2)
#define XSZ (TT*NTOK*DD)
#define USZ (EE*EFF*DD)
#define DSZ (EE*DD*EFF)
#define EPS 132
#define RSC (1.0f/2048.0f)

__device__ int g_count[EE];
__device__ int g_list[EE*CAP];
__device__ __half g_xl[(size_t)2*XSZ];   // x0, x1s(<<11)
__device__ __half g_uw[(size_t)2*USZ];   // u0, u1s
__device__ __half g_dw[(size_t)2*DSZ];   // d0, d1s
__device__ __half g_spk[(size_t)CAP*TT*EFF];

static __device__ __forceinline__ uint32_t s2u(const void* p) {
    uint32_t a;
    asm("{ .reg .u64 t; cvta.to.shared.u64 t, %1; cvt.u32.u64 %0, t; }" : "=r"(a) : "l"(p));
    return a;
}
#define CP16(dst, src) asm volatile("cp.async.cg.shared.global [%0], [%1], 16;" \
    :: "r"(dst), "l"(src) : "memory")
#define CPCOMMIT() asm volatile("cp.async.commit_group;" ::: "memory")
#define CPWAIT(n)  asm volatile("cp.async.wait_group %0;" :: "n"(n) : "memory")
#define LDSM4(r0,r1,r2,r3,addr) asm volatile( \
    "ldmatrix.sync.aligned.m8n8.x4.shared.b16 {%0,%1,%2,%3}, [%4];" \
    : "=r"(r0),"=r"(r1),"=r"(r2),"=r"(r3) : "r"(addr))
#define MMA(c, a, b) asm volatile( \
    "mma.sync.aligned.m16n8k16.row.col.f32.f16.f16.f32 " \
    "{%0,%1,%2,%3},{%4,%5,%6,%7},{%8,%9},{%0,%1,%2,%3};" \
    : "+f"((c)[0]),"+f"((c)[1]),"+f"((c)[2]),"+f"((c)[3]) \
    : "r"((a)[0]),"r"((a)[1]),"r"((a)[2]),"r"((a)[3]), "r"((b)[0]),"r"((b)[1]))

static __device__ __forceinline__ void lif4(float v0, float v1, float v2, float v3,
                                            float &s0, float &s1, float &s2, float &s3) {
    float m = v0;     s0 = (m > 1.0f) ? 1.0f : 0.0f; m -= s0;
    m = 0.9f*m + v1;  s1 = (m > 1.0f) ? 1.0f : 0.0f; m -= s1;
    m = 0.9f*m + v2;  s2 = (m > 1.0f) ? 1.0f : 0.0f; m -= s2;
    m = 0.9f*m + v3;  s3 = (m > 1.0f) ? 1.0f : 0.0f;
}

__global__ void reset_kernel() { if (threadIdx.x < EE) g_count[threadIdx.x] = 0; }

__global__ void route_kernel(const int* __restrict__ idx) {
    int n = blockIdx.x * blockDim.x + threadIdx.x;
    if (n >= NTOK) return;
    #pragma unroll
    for (int k = 0; k < TOPK; ++k) {
        int e = idx[n*TOPK + k];
        int p = atomicAdd(&g_count[e], 1);
        g_list[e*CAP + p] = (n << 1) | k;
    }
}

static __device__ __forceinline__ uint32_t hbits(__half h) {
    return (uint32_t)__half_as_ushort(h);
}

// which: 0 = x, 1 = up, 2 = down — all 2 planes {v0, v1s = (v - v0)*2048}
__global__ void split_kernel(const float* __restrict__ src, int n4, int which) {
    __half* d = (which == 0) ? g_xl : (which == 1) ? g_uw : g_dw;
    size_t sz = (which == 0) ? (size_t)XSZ : (which == 1) ? (size_t)USZ : (size_t)DSZ;
    int i = blockIdx.x * blockDim.x + threadIdx.x;
    if (i >= n4) return;
    float4 v = ((const float4*)src)[i];
    float a[4] = {v.x, v.y, v.z, v.w};
    uint32_t u0[4], u1[4];
    #pragma unroll
    for (int j = 0; j < 4; ++j) {
        __half h0 = __float2half_rn(a[j]);
        float r = a[j] - __half2float(h0);
        u0[j] = hbits(h0);
        u1[j] = hbits(__float2half_rn(r * 2048.0f));
    }
    ((uint2*)(d     ))[i] = make_uint2(u0[0]|(u0[1]<<16), u0[2]|(u0[3]<<16));
    ((uint2*)(d + sz))[i] = make_uint2(u1[0]|(u1[1]<<16), u1[2]|(u1[3]<<16));
}

// S=1: spikes = LIF(x@up^T); A {x0,x1s}, B {u0,u1s}
//      combos: (x0,u0)->H; (x0,u1s),(x1s,u0)->L.  val = H + L/2048
// S=2: out += w*LIF(spk@down^T); A {spk}, B {d0,d1s}: (s,d0)->H; (s,d1s)->L
template<int S>
__global__ __launch_bounds__(256, 1)
void gemm_lif(const float* __restrict__ ew, float* __restrict__ out) {
    constexpr int NA = (S == 1) ? 2 : 1;
    constexpr int NT = NA + 2;
    constexpr int KTOT = (S == 1) ? DD : EFF;
    constexpr size_t BSZ = (S == 1) ? (size_t)USZ : (size_t)DSZ;
    constexpr int BUF = NT * TILE_B;
    const int e = blockIdx.z, nc = blockIdx.y;
    const int cnt = g_count[e], start = blockIdx.x * MTOK;
    if (start >= cnt) return;

    extern __shared__ char dyn[];
    const uint32_t sb = s2u(dyn);
    __shared__ int s_ent[MTOK], s_ok[MTOK], s_rb[MR];
    __shared__ float s_w[MTOK];

    const int tid = threadIdx.x, lane = tid & 31, wid = tid >> 5;
    const int wm = wid & 1, wn = wid >> 1;
    if (tid < MTOK) {
        int i = start + tid, ok = (i < cnt) ? 1 : 0;
        int ent = g_list[e*CAP + (ok ? i : cnt - 1)];
        s_ent[tid] = ent; s_ok[tid] = ok; s_w[tid] = ew[ent];
    }
    __syncthreads();
    if (tid < MR) {
        int ent = s_ent[tid >> 2];
        s_rb[tid] = (S == 1) ? ((tid & 3)*NTOK + (ent >> 1))*DD
                             : ent*(TT*EFF) + (tid & 3)*EFF;
    }
    __syncthreads();

    const size_t wbase = (S == 1) ? ((size_t)e*EFF + (size_t)nc*128)*DD
                                  : ((size_t)e*DD  + (size_t)nc*128)*EFF;
    const __half* Bp = (S == 1) ? g_uw : g_dw;

    float aH[4][4][4], aL[4][4][4];
    #pragma unroll
    for (int mi = 0; mi < 4; ++mi)
        #pragma unroll
        for (int nj = 0; nj < 4; ++nj)
            #pragma unroll
            for (int q = 0; q < 4; ++q) { aH[mi][nj][q] = 0.0f; aL[mi][nj][q] = 0.0f; }

    const uint32_t aoff = (uint32_t)((wm*64 + (lane & 15))*(SA*2) + (lane >> 4)*16);
    const uint32_t boff = (uint32_t)((wn*32 + (lane & 15))*(SA*2) + (lane >> 4)*16);

    // ---- prologue: stage chunk 0 into buffer 0 ----
    #pragma unroll
    for (int u = 0; u < NT*2; ++u) {
        int q = u*256 + tid;
        int tile = q >> 9, idx = q & 511, row = idx >> 2, seg = idx & 3;
        const __half* src = (tile < NA)
            ? ((S == 1) ? g_xl + (size_t)tile*XSZ + s_rb[row] + seg*8
                        : g_spk + (size_t)s_rb[row] + seg*8)
            : Bp + (size_t)(tile - NA)*BSZ + wbase + (size_t)row*KTOT + seg*8;
        CP16(sb + tile*TILE_B + row*(SA*2) + seg*16, src);
    }
    CPCOMMIT();

    for (int kc = 0; kc < KTOT/32; ++kc) {
        if (kc + 1 < KTOT/32) {
            const int kb = (kc + 1) * 32;
            const uint32_t dstb = sb + ((kc + 1) & 1) * BUF;
            #pragma unroll
            for (int u = 0; u < NT*2; ++u) {
                int q = u*256 + tid;
                int tile = q >> 9, idx = q & 511, row = idx >> 2, seg = idx & 3;
                const __half* src = (tile < NA)
                    ? ((S == 1) ? g_xl + (size_t)tile*XSZ + s_rb[row] + kb + seg*8
                                : g_spk + (size_t)s_rb[row] + kb + seg*8)
                    : Bp + (size_t)(tile - NA)*BSZ + wbase + (size_t)row*KTOT + kb + seg*8;
                CP16(dstb + tile*TILE_B + row*(SA*2) + seg*16, src);
            }
            CPCOMMIT();
            CPWAIT(1);
        } else {
            CPWAIT(0);
        }
        __syncthreads();
        const uint32_t base = sb + (kc & 1) * BUF;
        #pragma unroll
        for (int k16 = 0; k16 < 2; ++k16) {
            const uint32_t ko = k16 * 32;
            uint32_t b[2][4][2];
            #pragma unroll
            for (int lb = 0; lb < 2; ++lb)
                #pragma unroll
                for (int g = 0; g < 2; ++g) {
                    uint32_t r0, r1, r2, r3;
                    LDSM4(r0, r1, r2, r3, base + (NA+lb)*TILE_B + boff + g*16*(SA*2) + ko);
                    b[lb][g*2+0][0] = r0; b[lb][g*2+0][1] = r2;
                    b[lb][g*2+1][0] = r1; b[lb][g*2+1][1] = r3;
                }
            #pragma unroll
            for (int la = 0; la < NA; ++la) {
                uint32_t a[4][4];
                #pragma unroll
                for (int mi = 0; mi < 4; ++mi)
                    LDSM4(a[mi][0], a[mi][1], a[mi][2], a[mi][3],
                          base + la*TILE_B + aoff + mi*16*(SA*2) + ko);
                if (la == 0) {
                    #pragma unroll
                    for (int mi = 0; mi < 4; ++mi)
                        #pragma unroll
                        for (int nj = 0; nj < 4; ++nj)
                            MMA(aH[mi][nj], a[mi], b[0][nj]);     // (0,0) -> H
                    #pragma unroll
                    for (int mi = 0; mi < 4; ++mi)
                        #pragma unroll
                        for (int nj = 0; nj < 4; ++nj)
                            MMA(aL[mi][nj], a[mi], b[1][nj]);     // (0,1s) -> L
                } else {
                    #pragma unroll
                    for (int mi = 0; mi < 4; ++mi)
                        #pragma unroll
                        for (int nj = 0; nj < 4; ++nj)
                            MMA(aL[mi][nj], a[mi], b[0][nj]);     // (1s,0) -> L
                }
            }
        }
        __syncthreads();
    }

    float* ep = (float*)dyn;
    #pragma unroll
    for (int mi = 0; mi < 4; ++mi)
        #pragma unroll
        for (int nj = 0; nj < 4; ++nj) {
            int R = wm*64 + mi*16 + (lane >> 2);
            int C = wn*32 + nj*8 + (lane & 3)*2;
            *(float2*)&ep[R*EPS + C] = make_float2(aH[mi][nj][0] + aL[mi][nj][0]*RSC,
                                                   aH[mi][nj][1] + aL[mi][nj][1]*RSC);
            *(float2*)&ep[(R+8)*EPS + C] = make_float2(aH[mi][nj][2] + aL[mi][nj][2]*RSC,
                                                       aH[mi][nj][3] + aL[mi][nj][3]*RSC);
        }
    __syncthreads();
    #pragma unroll
    for (int i = 0; i < 8; ++i) {
        int c = i*256 + tid;
        int sl = c >> 6, cp = c & 63;
        if (!s_ok[sl]) continue;
        float2 v0 = *(float2*)&ep[(sl*4+0)*EPS + cp*2];
        float2 v1 = *(float2*)&ep[(sl*4+1)*EPS + cp*2];
        float2 v2 = *(float2*)&ep[(sl*4+2)*EPS + cp*2];
        float2 v3 = *(float2*)&ep[(sl*4+3)*EPS + cp*2];
        float a0,a1,a2,a3, b0,b1,b2,b3;
        lif4(v0.x, v1.x, v2.x, v3.x, a0, a1, a2, a3);
        lif4(v0.y, v1.y, v2.y, v3.y, b0, b1, b2, b3);
        if (S == 1) {
            __half* spb = g_spk + (size_t)s_ent[sl]*(TT*EFF) + nc*128 + cp*2;
            uint32_t p0 = (a0 != 0.0f ? 0x3C00u : 0u) | (b0 != 0.0f ? 0x3C000000u : 0u);
            uint32_t p1 = (a1 != 0.0f ? 0x3C00u : 0u) | (b1 != 0.0f ? 0x3C000000u : 0u);
            uint32_t p2 = (a2 != 0.0f ? 0x3C00u : 0u) | (b2 != 0.0f ? 0x3C000000u : 0u);
            uint32_t p3 = (a3 != 0.0f ? 0x3C00u : 0u) | (b3 != 0.0f ? 0x3C000000u : 0u);
            *(uint32_t*)(spb + 0*EFF) = p0;
            *(uint32_t*)(spb + 1*EFF) = p1;
            *(uint32_t*)(spb + 2*EFF) = p2;
            *(uint32_t*)(spb + 3*EFF) = p3;
        } else {
            int n = s_ent[sl] >> 1;
            float w = s_w[sl];
            float s[4][2] = {{a0,b0},{a1,b1},{a2,b2},{a3,b3}};
            #pragma unroll
            for (int t = 0; t < 4; ++t) {
                float* ob = out + ((size_t)t*NTOK + n)*DD + nc*128 + cp*2;
                if (s[t][0] != 0.0f) atomicAdd(ob,     w);
                if (s[t][1] != 0.0f) atomicAdd(ob + 1, w);
            }
        }
    }
}

#define S1_SMEM (2*4*TILE_B)                       // 81920 >= epilogue 67584
#define S2_SMEM 69632                              // >= max(2*3*TILE_B=61440, 67584)

extern "C" void kernel_launch(void* const* d_in, const int* in_sizes, int n_in,
                              void* d_out, int out_size) {
    const float* x  = (const float*)d_in[0];
    const int*   ei = (const int*)  d_in[1];
    const float* ew = (const float*)d_in[2];
    const float* up = (const float*)d_in[3];
    const float* dw = (const float*)d_in[4];
    float* out = (float*)d_out;
    (void)in_sizes; (void)n_in;

    cudaFuncSetAttribute(gemm_lif<1>, cudaFuncAttributeMaxDynamicSharedMemorySize, S1_SMEM);
    cudaFuncSetAttribute(gemm_lif<2>, cudaFuncAttributeMaxDynamicSharedMemorySize, S2_SMEM);

    cudaMemsetAsync(d_out, 0, (size_t)out_size * sizeof(float), 0);
    reset_kernel<<<1, 32>>>();
    route_kernel<<<NTOK/256, 256>>>(ei);
    split_kernel<<<(XSZ/4 + 255)/256, 256>>>(x,  XSZ/4, 0);
    split_kernel<<<(USZ/4 + 255)/256, 256>>>(up, USZ/4, 1);
    split_kernel<<<(DSZ/4 + 255)/256, 256>>>(dw, DSZ/4, 2);
    gemm_lif<1><<<dim3(CAP/MTOK, EFF/128, EE), 256, S1_SMEM>>>(ew, out);
    gemm_lif<2><<<dim3(CAP/MTOK, DD/128,  EE), 256, S2_SMEM>>>(ew, out);
}

// round 13
// speedup vs baseline: 2.8785x; 1.0994x over previous
#include <cuda_runtime.h>
#include <cuda_fp16.h>
#include <cstdint>

#define TT 4
#define NTOK 8192
#define DD 1024
#define EE 8
#define EFF 512
#define TOPK 2
#define CAP (NTOK*TOPK)
#define MTOK 32
#define MR 128
#define KCH 64
#define SA 72
#define TILE_B (MR*SA*2)          // 18432 B per tile (128 rows x 144B)
#define XSZ (TT*NTOK*DD)
#define USZ (EE*EFF*DD)
#define DSZ (EE*DD*EFF)
#define EPS 132
#define RSC (1.0f/2048.0f)

__device__ int g_count[EE];
__device__ int g_list[EE*CAP];
__device__ __half g_xl[(size_t)2*XSZ];   // x0, x1s(<<11)
__device__ __half g_uw[(size_t)2*USZ];   // u0, u1s
__device__ __half g_dw[(size_t)2*DSZ];   // d0, d1s
__device__ __half g_spk[(size_t)CAP*TT*EFF];

static __device__ __forceinline__ uint32_t s2u(const void* p) {
    uint32_t a;
    asm("{ .reg .u64 t; cvta.to.shared.u64 t, %1; cvt.u32.u64 %0, t; }" : "=r"(a) : "l"(p));
    return a;
}
#define CP16(dst, src) asm volatile("cp.async.cg.shared.global [%0], [%1], 16;" \
    :: "r"(dst), "l"(src) : "memory")
#define CPCOMMIT() asm volatile("cp.async.commit_group;" ::: "memory")
#define CPWAIT(n)  asm volatile("cp.async.wait_group %0;" :: "n"(n) : "memory")
#define LDSM4(r0,r1,r2,r3,addr) asm volatile( \
    "ldmatrix.sync.aligned.m8n8.x4.shared.b16 {%0,%1,%2,%3}, [%4];" \
    : "=r"(r0),"=r"(r1),"=r"(r2),"=r"(r3) : "r"(addr))
#define MMA(c, a, b) asm volatile( \
    "mma.sync.aligned.m16n8k16.row.col.f32.f16.f16.f32 " \
    "{%0,%1,%2,%3},{%4,%5,%6,%7},{%8,%9},{%0,%1,%2,%3};" \
    : "+f"((c)[0]),"+f"((c)[1]),"+f"((c)[2]),"+f"((c)[3]) \
    : "r"((a)[0]),"r"((a)[1]),"r"((a)[2]),"r"((a)[3]), "r"((b)[0]),"r"((b)[1]))

static __device__ __forceinline__ void lif4(float v0, float v1, float v2, float v3,
                                            float &s0, float &s1, float &s2, float &s3) {
    float m = v0;     s0 = (m > 1.0f) ? 1.0f : 0.0f; m -= s0;
    m = 0.9f*m + v1;  s1 = (m > 1.0f) ? 1.0f : 0.0f; m -= s1;
    m = 0.9f*m + v2;  s2 = (m > 1.0f) ? 1.0f : 0.0f; m -= s2;
    m = 0.9f*m + v3;  s3 = (m > 1.0f) ? 1.0f : 0.0f;
}

__global__ void reset_kernel() { if (threadIdx.x < EE) g_count[threadIdx.x] = 0; }

__global__ void route_kernel(const int* __restrict__ idx) {
    int n = blockIdx.x * blockDim.x + threadIdx.x;
    if (n >= NTOK) return;
    #pragma unroll
    for (int k = 0; k < TOPK; ++k) {
        int e = idx[n*TOPK + k];
        int p = atomicAdd(&g_count[e], 1);
        g_list[e*CAP + p] = (n << 1) | k;
    }
}

static __device__ __forceinline__ uint32_t hbits(__half h) {
    return (uint32_t)__half_as_ushort(h);
}

// which: 0 = x, 1 = up, 2 = down — 2 planes {v0, v1s = (v - v0)*2048}
__global__ void split_kernel(const float* __restrict__ src, int n4, int which) {
    __half* d = (which == 0) ? g_xl : (which == 1) ? g_uw : g_dw;
    size_t sz = (which == 0) ? (size_t)XSZ : (which == 1) ? (size_t)USZ : (size_t)DSZ;
    int i = blockIdx.x * blockDim.x + threadIdx.x;
    if (i >= n4) return;
    float4 v = ((const float4*)src)[i];
    float a[4] = {v.x, v.y, v.z, v.w};
    uint32_t u0[4], u1[4];
    #pragma unroll
    for (int j = 0; j < 4; ++j) {
        __half h0 = __float2half_rn(a[j]);
        float r = a[j] - __half2float(h0);
        u0[j] = hbits(h0);
        u1[j] = hbits(__float2half_rn(r * 2048.0f));
    }
    ((uint2*)(d     ))[i] = make_uint2(u0[0]|(u0[1]<<16), u0[2]|(u0[3]<<16));
    ((uint2*)(d + sz))[i] = make_uint2(u1[0]|(u1[1]<<16), u1[2]|(u1[3]<<16));
}

// S=1: spikes = LIF(x@up^T); A {x0,x1s}, B {u0,u1s}
//      combos: (x0,u0)->H; (x0,u1s),(x1s,u0)->L.  val = H + L/2048
// S=2: out += w*LIF(spk@down^T); A {spk}, B {d0,d1s}: (s,d0)->H; (s,d1s)->L
template<int S>
__global__ __launch_bounds__(256, 1)
void gemm_lif(const float* __restrict__ ew, float* __restrict__ out) {
    constexpr int NA = (S == 1) ? 2 : 1;
    constexpr int NT = NA + 2;
    constexpr int KTOT = (S == 1) ? DD : EFF;
    constexpr size_t BSZ = (S == 1) ? (size_t)USZ : (size_t)DSZ;
    constexpr int BUF = NT * TILE_B;
    const int e = blockIdx.z, nc = blockIdx.y;
    const int cnt = g_count[e], start = blockIdx.x * MTOK;
    if (start >= cnt) return;

    extern __shared__ char dyn[];
    const uint32_t sb = s2u(dyn);
    __shared__ int s_ent[MTOK], s_ok[MTOK], s_rb[MR];
    __shared__ float s_w[MTOK];

    const int tid = threadIdx.x, lane = tid & 31, wid = tid >> 5;
    const int wm = wid & 1, wn = wid >> 1;
    if (tid < MTOK) {
        int i = start + tid, ok = (i < cnt) ? 1 : 0;
        int ent = g_list[e*CAP + (ok ? i : cnt - 1)];
        s_ent[tid] = ent; s_ok[tid] = ok; s_w[tid] = ew[ent];
    }
    __syncthreads();
    if (tid < MR) {
        int ent = s_ent[tid >> 2];
        s_rb[tid] = (S == 1) ? ((tid & 3)*NTOK + (ent >> 1))*DD
                             : ent*(TT*EFF) + (tid & 3)*EFF;
    }
    __syncthreads();

    const size_t wbase = (S == 1) ? ((size_t)e*EFF + (size_t)nc*128)*DD
                                  : ((size_t)e*DD  + (size_t)nc*128)*EFF;
    const __half* Bp = (S == 1) ? g_uw : g_dw;

    float aH[4][4][4], aL[4][4][4];
    #pragma unroll
    for (int mi = 0; mi < 4; ++mi)
        #pragma unroll
        for (int nj = 0; nj < 4; ++nj)
            #pragma unroll
            for (int q = 0; q < 4; ++q) { aH[mi][nj][q] = 0.0f; aL[mi][nj][q] = 0.0f; }

    const uint32_t aoff = (uint32_t)((wm*64 + (lane & 15))*(SA*2) + (lane >> 4)*16);
    const uint32_t boff = (uint32_t)((wn*32 + (lane & 15))*(SA*2) + (lane >> 4)*16);

    // ---- prologue: stage chunk 0 (KCH=64 cols) into buffer 0 ----
    #pragma unroll
    for (int u = 0; u < NT*4; ++u) {
        int q = u*256 + tid;
        int tile = q >> 10, idx = q & 1023, row = idx >> 3, seg = idx & 7;
        const __half* src = (tile < NA)
            ? ((S == 1) ? g_xl + (size_t)tile*XSZ + s_rb[row] + seg*8
                        : g_spk + (size_t)s_rb[row] + seg*8)
            : Bp + (size_t)(tile - NA)*BSZ + wbase + (size_t)row*KTOT + seg*8;
        CP16(sb + tile*TILE_B + row*(SA*2) + seg*16, src);
    }
    CPCOMMIT();

    for (int kc = 0; kc < KTOT/KCH; ++kc) {
        if (kc + 1 < KTOT/KCH) {
            const int kb = (kc + 1) * KCH;
            const uint32_t dstb = sb + ((kc + 1) & 1) * BUF;
            #pragma unroll
            for (int u = 0; u < NT*4; ++u) {
                int q = u*256 + tid;
                int tile = q >> 10, idx = q & 1023, row = idx >> 3, seg = idx & 7;
                const __half* src = (tile < NA)
                    ? ((S == 1) ? g_xl + (size_t)tile*XSZ + s_rb[row] + kb + seg*8
                                : g_spk + (size_t)s_rb[row] + kb + seg*8)
                    : Bp + (size_t)(tile - NA)*BSZ + wbase + (size_t)row*KTOT + kb + seg*8;
                CP16(dstb + tile*TILE_B + row*(SA*2) + seg*16, src);
            }
            CPCOMMIT();
            CPWAIT(1);
        } else {
            CPWAIT(0);
        }
        __syncthreads();
        const uint32_t base = sb + (kc & 1) * BUF;
        #pragma unroll
        for (int k16 = 0; k16 < 4; ++k16) {
            const uint32_t ko = k16 * 32;
            uint32_t b[2][4][2];
            #pragma unroll
            for (int lb = 0; lb < 2; ++lb)
                #pragma unroll
                for (int g = 0; g < 2; ++g) {
                    uint32_t r0, r1, r2, r3;
                    LDSM4(r0, r1, r2, r3, base + (NA+lb)*TILE_B + boff + g*16*(SA*2) + ko);
                    b[lb][g*2+0][0] = r0; b[lb][g*2+0][1] = r2;
                    b[lb][g*2+1][0] = r1; b[lb][g*2+1][1] = r3;
                }
            #pragma unroll
            for (int la = 0; la < NA; ++la) {
                uint32_t a[4][4];
                #pragma unroll
                for (int mi = 0; mi < 4; ++mi)
                    LDSM4(a[mi][0], a[mi][1], a[mi][2], a[mi][3],
                          base + la*TILE_B + aoff + mi*16*(SA*2) + ko);
                if (la == 0) {
                    #pragma unroll
                    for (int mi = 0; mi < 4; ++mi)
                        #pragma unroll
                        for (int nj = 0; nj < 4; ++nj)
                            MMA(aH[mi][nj], a[mi], b[0][nj]);     // (0,0) -> H
                    #pragma unroll
                    for (int mi = 0; mi < 4; ++mi)
                        #pragma unroll
                        for (int nj = 0; nj < 4; ++nj)
                            MMA(aL[mi][nj], a[mi], b[1][nj]);     // (0,1s) -> L
                } else {
                    #pragma unroll
                    for (int mi = 0; mi < 4; ++mi)
                        #pragma unroll
                        for (int nj = 0; nj < 4; ++nj)
                            MMA(aL[mi][nj], a[mi], b[0][nj]);     // (1s,0) -> L
                }
            }
        }
        __syncthreads();
    }

    float* ep = (float*)dyn;
    #pragma unroll
    for (int mi = 0; mi < 4; ++mi)
        #pragma unroll
        for (int nj = 0; nj < 4; ++nj) {
            int R = wm*64 + mi*16 + (lane >> 2);
            int C = wn*32 + nj*8 + (lane & 3)*2;
            *(float2*)&ep[R*EPS + C] = make_float2(aH[mi][nj][0] + aL[mi][nj][0]*RSC,
                                                   aH[mi][nj][1] + aL[mi][nj][1]*RSC);
            *(float2*)&ep[(R+8)*EPS + C] = make_float2(aH[mi][nj][2] + aL[mi][nj][2]*RSC,
                                                       aH[mi][nj][3] + aL[mi][nj][3]*RSC);
        }
    __syncthreads();
    #pragma unroll
    for (int i = 0; i < 8; ++i) {
        int c = i*256 + tid;
        int sl = c >> 6, cp = c & 63;
        if (!s_ok[sl]) continue;
        float2 v0 = *(float2*)&ep[(sl*4+0)*EPS + cp*2];
        float2 v1 = *(float2*)&ep[(sl*4+1)*EPS + cp*2];
        float2 v2 = *(float2*)&ep[(sl*4+2)*EPS + cp*2];
        float2 v3 = *(float2*)&ep[(sl*4+3)*EPS + cp*2];
        float a0,a1,a2,a3, b0,b1,b2,b3;
        lif4(v0.x, v1.x, v2.x, v3.x, a0, a1, a2, a3);
        lif4(v0.y, v1.y, v2.y, v3.y, b0, b1, b2, b3);
        if (S == 1) {
            __half* spb = g_spk + (size_t)s_ent[sl]*(TT*EFF) + nc*128 + cp*2;
            uint32_t p0 = (a0 != 0.0f ? 0x3C00u : 0u) | (b0 != 0.0f ? 0x3C000000u : 0u);
            uint32_t p1 = (a1 != 0.0f ? 0x3C00u : 0u) | (b1 != 0.0f ? 0x3C000000u : 0u);
            uint32_t p2 = (a2 != 0.0f ? 0x3C00u : 0u) | (b2 != 0.0f ? 0x3C000000u : 0u);
            uint32_t p3 = (a3 != 0.0f ? 0x3C00u : 0u) | (b3 != 0.0f ? 0x3C000000u : 0u);
            *(uint32_t*)(spb + 0*EFF) = p0;
            *(uint32_t*)(spb + 1*EFF) = p1;
            *(uint32_t*)(spb + 2*EFF) = p2;
            *(uint32_t*)(spb + 3*EFF) = p3;
        } else {
            int n = s_ent[sl] >> 1;
            float w = s_w[sl];
            float s[4][2] = {{a0,b0},{a1,b1},{a2,b2},{a3,b3}};
            #pragma unroll
            for (int t = 0; t < 4; ++t) {
                float* ob = out + ((size_t)t*NTOK + n)*DD + nc*128 + cp*2;
                if (s[t][0] != 0.0f) atomicAdd(ob,     w);
                if (s[t][1] != 0.0f) atomicAdd(ob + 1, w);
            }
        }
    }
}

#define S1_SMEM (2*4*TILE_B)                       // 147456 >= epilogue 67584
#define S2_SMEM (2*3*TILE_B)                       // 110592 >= 67584

extern "C" void kernel_launch(void* const* d_in, const int* in_sizes, int n_in,
                              void* d_out, int out_size) {
    const float* x  = (const float*)d_in[0];
    const int*   ei = (const int*)  d_in[1];
    const float* ew = (const float*)d_in[2];
    const float* up = (const float*)d_in[3];
    const float* dw = (const float*)d_in[4];
    float* out = (float*)d_out;
    (void)in_sizes; (void)n_in;

    cudaFuncSetAttribute(gemm_lif<1>, cudaFuncAttributeMaxDynamicSharedMemorySize, S1_SMEM);
    cudaFuncSetAttribute(gemm_lif<2>, cudaFuncAttributeMaxDynamicSharedMemorySize, S2_SMEM);

    cudaMemsetAsync(d_out, 0, (size_t)out_size * sizeof(float), 0);
    reset_kernel<<<1, 32>>>();
    route_kernel<<<NTOK/256, 256>>>(ei);
    split_kernel<<<(XSZ/4 + 255)/256, 256>>>(x,  XSZ/4, 0);
    split_kernel<<<(USZ/4 + 255)/256, 256>>>(up, USZ/4, 1);
    split_kernel<<<(DSZ/4 + 255)/256, 256>>>(dw, DSZ/4, 2);
    gemm_lif<1><<<dim3(CAP/MTOK, EFF/128, EE), 256, S1_SMEM>>>(ew, out);
    gemm_lif<2><<<dim3(CAP/MTOK, DD/128,  EE), 256, S2_SMEM>>>(ew, out);
}

// round 14
// speedup vs baseline: 2.8936x; 1.0052x over previous
#include <cuda_runtime.h>
#include <cuda_fp16.h>
#include <cstdint>

#define TT 4
#define NTOK 8192
#define DD 1024
#define EE 8
#define EFF 512
#define TOPK 2
#define CAP (NTOK*TOPK)
#define MTOK 32
#define MR 128
#define KCH 64
#define SA 72
#define TILE_B (MR*SA*2)          // 18432 B per tile (128 rows x 144B)
#define XSZ (TT*NTOK*DD)
#define USZ (EE*EFF*DD)
#define DSZ (EE*DD*EFF)
#define EPS 132
#define RSC (1.0f/2048.0f)

__device__ int g_count[EE];
__device__ int g_list[EE*CAP];
__device__ __half g_xl[(size_t)2*XSZ];   // x0, x1s(<<11)
__device__ __half g_uw[(size_t)2*USZ];   // u0, u1s
__device__ __half g_dw[(size_t)2*DSZ];   // d0, d1s
__device__ __half g_spk[(size_t)CAP*TT*EFF];

static __device__ __forceinline__ uint32_t s2u(const void* p) {
    uint32_t a;
    asm("{ .reg .u64 t; cvta.to.shared.u64 t, %1; cvt.u32.u64 %0, t; }" : "=r"(a) : "l"(p));
    return a;
}
#define CP16(dst, src) asm volatile("cp.async.cg.shared.global [%0], [%1], 16;" \
    :: "r"(dst), "l"(src) : "memory")
#define CPCOMMIT() asm volatile("cp.async.commit_group;" ::: "memory")
#define CPWAIT(n)  asm volatile("cp.async.wait_group %0;" :: "n"(n) : "memory")
#define LDSM4(r0,r1,r2,r3,addr) asm volatile( \
    "ldmatrix.sync.aligned.m8n8.x4.shared.b16 {%0,%1,%2,%3}, [%4];" \
    : "=r"(r0),"=r"(r1),"=r"(r2),"=r"(r3) : "r"(addr))
#define MMA(c, a, b) asm volatile( \
    "mma.sync.aligned.m16n8k16.row.col.f32.f16.f16.f32 " \
    "{%0,%1,%2,%3},{%4,%5,%6,%7},{%8,%9},{%0,%1,%2,%3};" \
    : "+f"((c)[0]),"+f"((c)[1]),"+f"((c)[2]),"+f"((c)[3]) \
    : "r"((a)[0]),"r"((a)[1]),"r"((a)[2]),"r"((a)[3]), "r"((b)[0]),"r"((b)[1]))

static __device__ __forceinline__ void lif4(float v0, float v1, float v2, float v3,
                                            float &s0, float &s1, float &s2, float &s3) {
    float m = v0;     s0 = (m > 1.0f) ? 1.0f : 0.0f; m -= s0;
    m = 0.9f*m + v1;  s1 = (m > 1.0f) ? 1.0f : 0.0f; m -= s1;
    m = 0.9f*m + v2;  s2 = (m > 1.0f) ? 1.0f : 0.0f; m -= s2;
    m = 0.9f*m + v3;  s3 = (m > 1.0f) ? 1.0f : 0.0f;
}

__global__ void reset_kernel() { if (threadIdx.x < EE) g_count[threadIdx.x] = 0; }

__global__ void route_kernel(const int* __restrict__ idx) {
    int n = blockIdx.x * blockDim.x + threadIdx.x;
    if (n >= NTOK) return;
    #pragma unroll
    for (int k = 0; k < TOPK; ++k) {
        int e = idx[n*TOPK + k];
        int p = atomicAdd(&g_count[e], 1);
        g_list[e*CAP + p] = (n << 1) | k;
    }
}

static __device__ __forceinline__ uint32_t hbits(__half h) {
    return (uint32_t)__half_as_ushort(h);
}

// which: 0 = x, 1 = up, 2 = down — 2 planes {v0, v1s = (v - v0)*2048}
__global__ void split_kernel(const float* __restrict__ src, int n4, int which) {
    __half* d = (which == 0) ? g_xl : (which == 1) ? g_uw : g_dw;
    size_t sz = (which == 0) ? (size_t)XSZ : (which == 1) ? (size_t)USZ : (size_t)DSZ;
    int i = blockIdx.x * blockDim.x + threadIdx.x;
    if (i >= n4) return;
    float4 v = ((const float4*)src)[i];
    float a[4] = {v.x, v.y, v.z, v.w};
    uint32_t u0[4], u1[4];
    #pragma unroll
    for (int j = 0; j < 4; ++j) {
        __half h0 = __float2half_rn(a[j]);
        float r = a[j] - __half2float(h0);
        u0[j] = hbits(h0);
        u1[j] = hbits(__float2half_rn(r * 2048.0f));
    }
    ((uint2*)(d     ))[i] = make_uint2(u0[0]|(u0[1]<<16), u0[2]|(u0[3]<<16));
    ((uint2*)(d + sz))[i] = make_uint2(u1[0]|(u1[1]<<16), u1[2]|(u1[3]<<16));
}

// S=1: spikes = LIF(x@up^T); A {x0,x1s}, B {u0,u1s}
//      combos: (x0,u0)->H; (x0,u1s),(x1s,u0)->L.  val = H + L/2048
// S=2: out += w*LIF(spk@down^T); A {spk}, B {d0,d1s}: (s,d0)->H; (s,d1s)->L
// 3-stage cp.async pipeline, ONE __syncthreads per K-chunk:
//   iter kc: wait(kc ready) -> bar -> stage(kc+2) -> compute(kc)
// stage(kc+2) writes buf[(kc+2)%3] = buf[(kc-1)%3], whose last readers
// (compute(kc-1)) all passed this iteration's bar.
template<int S>
__global__ __launch_bounds__(256, 1)
void gemm_lif(const float* __restrict__ ew, float* __restrict__ out) {
    constexpr int NA = (S == 1) ? 2 : 1;
    constexpr int NT = NA + 2;
    constexpr int KTOT = (S == 1) ? DD : EFF;
    constexpr int NC = KTOT / KCH;
    constexpr size_t BSZ = (S == 1) ? (size_t)USZ : (size_t)DSZ;
    constexpr int BUF = NT * TILE_B;
    const int e = blockIdx.z, nc = blockIdx.y;
    const int cnt = g_count[e], start = blockIdx.x * MTOK;
    if (start >= cnt) return;

    extern __shared__ char dyn[];
    const uint32_t sb = s2u(dyn);
    __shared__ int s_ent[MTOK], s_ok[MTOK], s_rb[MR];
    __shared__ float s_w[MTOK];

    const int tid = threadIdx.x, lane = tid & 31, wid = tid >> 5;
    const int wm = wid & 1, wn = wid >> 1;
    if (tid < MTOK) {
        int i = start + tid, ok = (i < cnt) ? 1 : 0;
        int ent = g_list[e*CAP + (ok ? i : cnt - 1)];
        s_ent[tid] = ent; s_ok[tid] = ok; s_w[tid] = ew[ent];
    }
    __syncthreads();
    if (tid < MR) {
        int ent = s_ent[tid >> 2];
        s_rb[tid] = (S == 1) ? ((tid & 3)*NTOK + (ent >> 1))*DD
                             : ent*(TT*EFF) + (tid & 3)*EFF;
    }
    __syncthreads();

    const size_t wbase = (S == 1) ? ((size_t)e*EFF + (size_t)nc*128)*DD
                                  : ((size_t)e*DD  + (size_t)nc*128)*EFF;
    const __half* Bp = (S == 1) ? g_uw : g_dw;

    float aH[4][4][4], aL[4][4][4];
    #pragma unroll
    for (int mi = 0; mi < 4; ++mi)
        #pragma unroll
        for (int nj = 0; nj < 4; ++nj)
            #pragma unroll
            for (int q = 0; q < 4; ++q) { aH[mi][nj][q] = 0.0f; aL[mi][nj][q] = 0.0f; }

    const uint32_t aoff = (uint32_t)((wm*64 + (lane & 15))*(SA*2) + (lane >> 4)*16);
    const uint32_t boff = (uint32_t)((wn*32 + (lane & 15))*(SA*2) + (lane >> 4)*16);

    // ---- staging helper (macro to keep addressing identical everywhere) ----
#define STAGE_CHUNK(CK, DSTB) do {                                                     \
        const int _kb = (CK) * KCH;                                                    \
        _Pragma("unroll")                                                              \
        for (int u = 0; u < NT*4; ++u) {                                               \
            int q = u*256 + tid;                                                       \
            int tile = q >> 10, idx = q & 1023, row = idx >> 3, seg = idx & 7;         \
            const __half* src = (tile < NA)                                            \
                ? ((S == 1) ? g_xl + (size_t)tile*XSZ + s_rb[row] + _kb + seg*8        \
                            : g_spk + (size_t)s_rb[row] + _kb + seg*8)                 \
                : Bp + (size_t)(tile - NA)*BSZ + wbase + (size_t)row*KTOT + _kb + seg*8; \
            CP16((DSTB) + tile*TILE_B + row*(SA*2) + seg*16, src);                     \
        }                                                                              \
        CPCOMMIT();                                                                    \
    } while (0)

    // ---- prologue: stage chunks 0 and 1 ----
    STAGE_CHUNK(0, sb);
    STAGE_CHUNK(1, sb + BUF);

    for (int kc = 0; kc < NC; ++kc) {
        if (kc + 1 < NC) { CPWAIT(1); } else { CPWAIT(0); }
        __syncthreads();
        if (kc + 2 < NC) {
            const uint32_t dstb = sb + ((kc + 2) % 3) * BUF;
            STAGE_CHUNK(kc + 2, dstb);
        }
        const uint32_t base = sb + (kc % 3) * BUF;
        #pragma unroll
        for (int k16 = 0; k16 < 4; ++k16) {
            const uint32_t ko = k16 * 32;
            uint32_t b[2][4][2];
            #pragma unroll
            for (int lb = 0; lb < 2; ++lb)
                #pragma unroll
                for (int g = 0; g < 2; ++g) {
                    uint32_t r0, r1, r2, r3;
                    LDSM4(r0, r1, r2, r3, base + (NA+lb)*TILE_B + boff + g*16*(SA*2) + ko);
                    b[lb][g*2+0][0] = r0; b[lb][g*2+0][1] = r2;
                    b[lb][g*2+1][0] = r1; b[lb][g*2+1][1] = r3;
                }
            #pragma unroll
            for (int la = 0; la < NA; ++la) {
                uint32_t a[4][4];
                #pragma unroll
                for (int mi = 0; mi < 4; ++mi)
                    LDSM4(a[mi][0], a[mi][1], a[mi][2], a[mi][3],
                          base + la*TILE_B + aoff + mi*16*(SA*2) + ko);
                if (la == 0) {
                    #pragma unroll
                    for (int mi = 0; mi < 4; ++mi)
                        #pragma unroll
                        for (int nj = 0; nj < 4; ++nj)
                            MMA(aH[mi][nj], a[mi], b[0][nj]);     // (0,0) -> H
                    #pragma unroll
                    for (int mi = 0; mi < 4; ++mi)
                        #pragma unroll
                        for (int nj = 0; nj < 4; ++nj)
                            MMA(aL[mi][nj], a[mi], b[1][nj]);     // (0,1s) -> L
                } else {
                    #pragma unroll
                    for (int mi = 0; mi < 4; ++mi)
                        #pragma unroll
                        for (int nj = 0; nj < 4; ++nj)
                            MMA(aL[mi][nj], a[mi], b[0][nj]);     // (1s,0) -> L
                }
            }
        }
    }
    __syncthreads();

    float* ep = (float*)dyn;
    #pragma unroll
    for (int mi = 0; mi < 4; ++mi)
        #pragma unroll
        for (int nj = 0; nj < 4; ++nj) {
            int R = wm*64 + mi*16 + (lane >> 2);
            int C = wn*32 + nj*8 + (lane & 3)*2;
            *(float2*)&ep[R*EPS + C] = make_float2(aH[mi][nj][0] + aL[mi][nj][0]*RSC,
                                                   aH[mi][nj][1] + aL[mi][nj][1]*RSC);
            *(float2*)&ep[(R+8)*EPS + C] = make_float2(aH[mi][nj][2] + aL[mi][nj][2]*RSC,
                                                       aH[mi][nj][3] + aL[mi][nj][3]*RSC);
        }
    __syncthreads();
    #pragma unroll
    for (int i = 0; i < 8; ++i) {
        int c = i*256 + tid;
        int sl = c >> 6, cp = c & 63;
        if (!s_ok[sl]) continue;
        float2 v0 = *(float2*)&ep[(sl*4+0)*EPS + cp*2];
        float2 v1 = *(float2*)&ep[(sl*4+1)*EPS + cp*2];
        float2 v2 = *(float2*)&ep[(sl*4+2)*EPS + cp*2];
        float2 v3 = *(float2*)&ep[(sl*4+3)*EPS + cp*2];
        float a0,a1,a2,a3, b0,b1,b2,b3;
        lif4(v0.x, v1.x, v2.x, v3.x, a0, a1, a2, a3);
        lif4(v0.y, v1.y, v2.y, v3.y, b0, b1, b2, b3);
        if (S == 1) {
            __half* spb = g_spk + (size_t)s_ent[sl]*(TT*EFF) + nc*128 + cp*2;
            uint32_t p0 = (a0 != 0.0f ? 0x3C00u : 0u) | (b0 != 0.0f ? 0x3C000000u : 0u);
            uint32_t p1 = (a1 != 0.0f ? 0x3C00u : 0u) | (b1 != 0.0f ? 0x3C000000u : 0u);
            uint32_t p2 = (a2 != 0.0f ? 0x3C00u : 0u) | (b2 != 0.0f ? 0x3C000000u : 0u);
            uint32_t p3 = (a3 != 0.0f ? 0x3C00u : 0u) | (b3 != 0.0f ? 0x3C000000u : 0u);
            *(uint32_t*)(spb + 0*EFF) = p0;
            *(uint32_t*)(spb + 1*EFF) = p1;
            *(uint32_t*)(spb + 2*EFF) = p2;
            *(uint32_t*)(spb + 3*EFF) = p3;
        } else {
            int n = s_ent[sl] >> 1;
            float w = s_w[sl];
            float s[4][2] = {{a0,b0},{a1,b1},{a2,b2},{a3,b3}};
            #pragma unroll
            for (int t = 0; t < 4; ++t) {
                float* ob = out + ((size_t)t*NTOK + n)*DD + nc*128 + cp*2;
                if (s[t][0] != 0.0f) atomicAdd(ob,     w);
                if (s[t][1] != 0.0f) atomicAdd(ob + 1, w);
            }
        }
    }
#undef STAGE_CHUNK
}

#define S1_SMEM (3*4*TILE_B)                       // 221184 (3-stage) >= epilogue 67584
#define S2_SMEM (3*3*TILE_B)                       // 165888 >= 67584

extern "C" void kernel_launch(void* const* d_in, const int* in_sizes, int n_in,
                              void* d_out, int out_size) {
    const float* x  = (const float*)d_in[0];
    const int*   ei = (const int*)  d_in[1];
    const float* ew = (const float*)d_in[2];
    const float* up = (const float*)d_in[3];
    const float* dw = (const float*)d_in[4];
    float* out = (float*)d_out;
    (void)in_sizes; (void)n_in;

    cudaFuncSetAttribute(gemm_lif<1>, cudaFuncAttributeMaxDynamicSharedMemorySize, S1_SMEM);
    cudaFuncSetAttribute(gemm_lif<2>, cudaFuncAttributeMaxDynamicSharedMemorySize, S2_SMEM);

    cudaMemsetAsync(d_out, 0, (size_t)out_size * sizeof(float), 0);
    reset_kernel<<<1, 32>>>();
    route_kernel<<<NTOK/256, 256>>>(ei);
    split_kernel<<<(XSZ/4 + 255)/256, 256>>>(x,  XSZ/4, 0);
    split_kernel<<<(USZ/4 + 255)/256, 256>>>(up, USZ/4, 1);
    split_kernel<<<(DSZ/4 + 255)/256, 256>>>(dw, DSZ/4, 2);
    gemm_lif<1><<<dim3(CAP/MTOK, EFF/128, EE), 256, S1_SMEM>>>(ew, out);
    gemm_lif<2><<<dim3(CAP/MTOK, DD/128,  EE), 256, S2_SMEM>>>(ew, out);
}

// round 15
// speedup vs baseline: 2.9067x; 1.0045x over previous
#include <cuda_runtime.h>
#include <cuda_fp16.h>
#include <cstdint>

#define TT 4
#define NTOK 8192
#define DD 1024
#define EE 8
#define EFF 512
#define TOPK 2
#define CAP (NTOK*TOPK)
#define MTOK 32
#define MR 128
#define KCH 64
#define SA 72
#define TILE_B (MR*SA*2)          // 18432 B per tile (128 rows x 144B)
#define XSZ (TT*NTOK*DD)
#define USZ (EE*EFF*DD)
#define DSZ (EE*DD*EFF)
#define EPS 132
#define RSC (1.0f/2048.0f)

__device__ int g_count[EE];
__device__ int g_list[EE*CAP];
__device__ __half g_xl[(size_t)2*XSZ];   // x0, x1s(<<11)
__device__ __half g_uw[(size_t)2*USZ];   // u0, u1s
__device__ __half g_dw[(size_t)2*DSZ];   // d0, d1s
__device__ __half g_spk[(size_t)CAP*TT*EFF];

static __device__ __forceinline__ uint32_t s2u(const void* p) {
    uint32_t a;
    asm("{ .reg .u64 t; cvta.to.shared.u64 t, %1; cvt.u32.u64 %0, t; }" : "=r"(a) : "l"(p));
    return a;
}
#define CP16(dst, src) asm volatile("cp.async.cg.shared.global [%0], [%1], 16;" \
    :: "r"(dst), "l"(src) : "memory")
#define CPCOMMIT() asm volatile("cp.async.commit_group;" ::: "memory")
#define CPWAIT(n)  asm volatile("cp.async.wait_group %0;" :: "n"(n) : "memory")
#define LDSM4(r0,r1,r2,r3,addr) asm volatile( \
    "ldmatrix.sync.aligned.m8n8.x4.shared.b16 {%0,%1,%2,%3}, [%4];" \
    : "=r"(r0),"=r"(r1),"=r"(r2),"=r"(r3) : "r"(addr))
#define MMA(c, a, b) asm volatile( \
    "mma.sync.aligned.m16n8k16.row.col.f32.f16.f16.f32 " \
    "{%0,%1,%2,%3},{%4,%5,%6,%7},{%8,%9},{%0,%1,%2,%3};" \
    : "+f"((c)[0]),"+f"((c)[1]),"+f"((c)[2]),"+f"((c)[3]) \
    : "r"((a)[0]),"r"((a)[1]),"r"((a)[2]),"r"((a)[3]), "r"((b)[0]),"r"((b)[1]))

static __device__ __forceinline__ void lif4(float v0, float v1, float v2, float v3,
                                            float &s0, float &s1, float &s2, float &s3) {
    float m = v0;     s0 = (m > 1.0f) ? 1.0f : 0.0f; m -= s0;
    m = 0.9f*m + v1;  s1 = (m > 1.0f) ? 1.0f : 0.0f; m -= s1;
    m = 0.9f*m + v2;  s2 = (m > 1.0f) ? 1.0f : 0.0f; m -= s2;
    m = 0.9f*m + v3;  s3 = (m > 1.0f) ? 1.0f : 0.0f;
}

__global__ void reset_kernel() { if (threadIdx.x < EE) g_count[threadIdx.x] = 0; }

__global__ void route_kernel(const int* __restrict__ idx) {
    int n = blockIdx.x * blockDim.x + threadIdx.x;
    if (n >= NTOK) return;
    #pragma unroll
    for (int k = 0; k < TOPK; ++k) {
        int e = idx[n*TOPK + k];
        int p = atomicAdd(&g_count[e], 1);
        g_list[e*CAP + p] = (n << 1) | k;
    }
}

static __device__ __forceinline__ uint32_t hbits(__half h) {
    return (uint32_t)__half_as_ushort(h);
}

// Fused split: one launch covers x | up | down (concatenated 8-float groups).
// Per element (identical math to prior rounds): h0 = fl16(v); h1s = fl16((v-h0)*2048).
#define NX8 (XSZ/8)
#define NU8 (USZ/8)
#define ND8 (DSZ/8)
__global__ void split_all_kernel(const float* __restrict__ x,
                                 const float* __restrict__ up,
                                 const float* __restrict__ dw) {
    size_t i = (size_t)blockIdx.x * blockDim.x + threadIdx.x;
    if (i >= (size_t)(NX8 + NU8 + ND8)) return;
    const float* src;
    __half* d;
    size_t sz;
    if (i < NX8)            { src = x  + i*8;              d = g_xl + i*8;              sz = XSZ; }
    else if (i < NX8 + NU8) { size_t j = i - NX8;          src = up + j*8; d = g_uw + j*8; sz = USZ; }
    else                    { size_t j = i - NX8 - NU8;    src = dw + j*8; d = g_dw + j*8; sz = DSZ; }
    float4 v0 = ((const float4*)src)[0];
    float4 v1 = ((const float4*)src)[1];
    float a[8] = {v0.x, v0.y, v0.z, v0.w, v1.x, v1.y, v1.z, v1.w};
    uint32_t p0[4], p1[4];
    #pragma unroll
    for (int j = 0; j < 4; ++j) {
        __half h0a = __float2half_rn(a[2*j]);
        __half h0b = __float2half_rn(a[2*j+1]);
        float ra = a[2*j]   - __half2float(h0a);
        float rb = a[2*j+1] - __half2float(h0b);
        p0[j] = hbits(h0a) | (hbits(h0b) << 16);
        p1[j] = hbits(__float2half_rn(ra * 2048.0f))
              | (hbits(__float2half_rn(rb * 2048.0f)) << 16);
    }
    *(uint4*)(d)      = make_uint4(p0[0], p0[1], p0[2], p0[3]);
    *(uint4*)(d + sz) = make_uint4(p1[0], p1[1], p1[2], p1[3]);
}

// S=1: spikes = LIF(x@up^T); A {x0,x1s}, B {u0,u1s}
//      combos: (x0,u0)->H; (x0,u1s),(x1s,u0)->L.  val = H + L/2048
// S=2: out += w*LIF(spk@down^T); A {spk}, B {d0,d1s}: (s,d0)->H; (s,d1s)->L
// 3-stage cp.async pipeline, ONE __syncthreads per K-chunk:
//   iter kc: wait(kc ready) -> bar -> stage(kc+2) -> compute(kc)
template<int S>
__global__ __launch_bounds__(256, 1)
void gemm_lif(const float* __restrict__ ew, float* __restrict__ out) {
    constexpr int NA = (S == 1) ? 2 : 1;
    constexpr int NT = NA + 2;
    constexpr int KTOT = (S == 1) ? DD : EFF;
    constexpr int NC = KTOT / KCH;
    constexpr size_t BSZ = (S == 1) ? (size_t)USZ : (size_t)DSZ;
    constexpr int BUF = NT * TILE_B;
    const int e = blockIdx.z, nc = blockIdx.y;
    const int cnt = g_count[e], start = blockIdx.x * MTOK;
    if (start >= cnt) return;

    extern __shared__ char dyn[];
    const uint32_t sb = s2u(dyn);
    __shared__ int s_ent[MTOK], s_ok[MTOK], s_rb[MR];
    __shared__ float s_w[MTOK];

    const int tid = threadIdx.x, lane = tid & 31, wid = tid >> 5;
    const int wm = wid & 1, wn = wid >> 1;
    if (tid < MTOK) {
        int i = start + tid, ok = (i < cnt) ? 1 : 0;
        int ent = g_list[e*CAP + (ok ? i : cnt - 1)];
        s_ent[tid] = ent; s_ok[tid] = ok; s_w[tid] = ew[ent];
    }
    __syncthreads();
    if (tid < MR) {
        int ent = s_ent[tid >> 2];
        s_rb[tid] = (S == 1) ? ((tid & 3)*NTOK + (ent >> 1))*DD
                             : ent*(TT*EFF) + (tid & 3)*EFF;
    }
    __syncthreads();

    const size_t wbase = (S == 1) ? ((size_t)e*EFF + (size_t)nc*128)*DD
                                  : ((size_t)e*DD  + (size_t)nc*128)*EFF;
    const __half* Bp = (S == 1) ? g_uw : g_dw;

    float aH[4][4][4], aL[4][4][4];
    #pragma unroll
    for (int mi = 0; mi < 4; ++mi)
        #pragma unroll
        for (int nj = 0; nj < 4; ++nj)
            #pragma unroll
            for (int q = 0; q < 4; ++q) { aH[mi][nj][q] = 0.0f; aL[mi][nj][q] = 0.0f; }

    const uint32_t aoff = (uint32_t)((wm*64 + (lane & 15))*(SA*2) + (lane >> 4)*16);
    const uint32_t boff = (uint32_t)((wn*32 + (lane & 15))*(SA*2) + (lane >> 4)*16);

#define STAGE_CHUNK(CK, DSTB) do {                                                     \
        const int _kb = (CK) * KCH;                                                    \
        _Pragma("unroll")                                                              \
        for (int u = 0; u < NT*4; ++u) {                                               \
            int q = u*256 + tid;                                                       \
            int tile = q >> 10, idx = q & 1023, row = idx >> 3, seg = idx & 7;         \
            const __half* src = (tile < NA)                                            \
                ? ((S == 1) ? g_xl + (size_t)tile*XSZ + s_rb[row] + _kb + seg*8        \
                            : g_spk + (size_t)s_rb[row] + _kb + seg*8)                 \
                : Bp + (size_t)(tile - NA)*BSZ + wbase + (size_t)row*KTOT + _kb + seg*8; \
            CP16((DSTB) + tile*TILE_B + row*(SA*2) + seg*16, src);                     \
        }                                                                              \
        CPCOMMIT();                                                                    \
    } while (0)

    STAGE_CHUNK(0, sb);
    STAGE_CHUNK(1, sb + BUF);

    for (int kc = 0; kc < NC; ++kc) {
        if (kc + 1 < NC) { CPWAIT(1); } else { CPWAIT(0); }
        __syncthreads();
        if (kc + 2 < NC) {
            const uint32_t dstb = sb + ((kc + 2) % 3) * BUF;
            STAGE_CHUNK(kc + 2, dstb);
        }
        const uint32_t base = sb + (kc % 3) * BUF;
        #pragma unroll
        for (int k16 = 0; k16 < 4; ++k16) {
            const uint32_t ko = k16 * 32;
            uint32_t b[2][4][2];
            #pragma unroll
            for (int lb = 0; lb < 2; ++lb)
                #pragma unroll
                for (int g = 0; g < 2; ++g) {
                    uint32_t r0, r1, r2, r3;
                    LDSM4(r0, r1, r2, r3, base + (NA+lb)*TILE_B + boff + g*16*(SA*2) + ko);
                    b[lb][g*2+0][0] = r0; b[lb][g*2+0][1] = r2;
                    b[lb][g*2+1][0] = r1; b[lb][g*2+1][1] = r3;
                }
            #pragma unroll
            for (int la = 0; la < NA; ++la) {
                uint32_t a[4][4];
                #pragma unroll
                for (int mi = 0; mi < 4; ++mi)
                    LDSM4(a[mi][0], a[mi][1], a[mi][2], a[mi][3],
                          base + la*TILE_B + aoff + mi*16*(SA*2) + ko);
                if (la == 0) {
                    #pragma unroll
                    for (int mi = 0; mi < 4; ++mi)
                        #pragma unroll
                        for (int nj = 0; nj < 4; ++nj)
                            MMA(aH[mi][nj], a[mi], b[0][nj]);     // (0,0) -> H
                    #pragma unroll
                    for (int mi = 0; mi < 4; ++mi)
                        #pragma unroll
                        for (int nj = 0; nj < 4; ++nj)
                            MMA(aL[mi][nj], a[mi], b[1][nj]);     // (0,1s) -> L
                } else {
                    #pragma unroll
                    for (int mi = 0; mi < 4; ++mi)
                        #pragma unroll
                        for (int nj = 0; nj < 4; ++nj)
                            MMA(aL[mi][nj], a[mi], b[0][nj]);     // (1s,0) -> L
                }
            }
        }
    }
    __syncthreads();

    float* ep = (float*)dyn;
    #pragma unroll
    for (int mi = 0; mi < 4; ++mi)
        #pragma unroll
        for (int nj = 0; nj < 4; ++nj) {
            int R = wm*64 + mi*16 + (lane >> 2);
            int C = wn*32 + nj*8 + (lane & 3)*2;
            *(float2*)&ep[R*EPS + C] = make_float2(aH[mi][nj][0] + aL[mi][nj][0]*RSC,
                                                   aH[mi][nj][1] + aL[mi][nj][1]*RSC);
            *(float2*)&ep[(R+8)*EPS + C] = make_float2(aH[mi][nj][2] + aL[mi][nj][2]*RSC,
                                                       aH[mi][nj][3] + aL[mi][nj][3]*RSC);
        }
    __syncthreads();
    #pragma unroll
    for (int i = 0; i < 8; ++i) {
        int c = i*256 + tid;
        int sl = c >> 6, cp = c & 63;
        if (!s_ok[sl]) continue;
        float2 v0 = *(float2*)&ep[(sl*4+0)*EPS + cp*2];
        float2 v1 = *(float2*)&ep[(sl*4+1)*EPS + cp*2];
        float2 v2 = *(float2*)&ep[(sl*4+2)*EPS + cp*2];
        float2 v3 = *(float2*)&ep[(sl*4+3)*EPS + cp*2];
        float a0,a1,a2,a3, b0,b1,b2,b3;
        lif4(v0.x, v1.x, v2.x, v3.x, a0, a1, a2, a3);
        lif4(v0.y, v1.y, v2.y, v3.y, b0, b1, b2, b3);
        if (S == 1) {
            __half* spb = g_spk + (size_t)s_ent[sl]*(TT*EFF) + nc*128 + cp*2;
            uint32_t p0 = (a0 != 0.0f ? 0x3C00u : 0u) | (b0 != 0.0f ? 0x3C000000u : 0u);
            uint32_t p1 = (a1 != 0.0f ? 0x3C00u : 0u) | (b1 != 0.0f ? 0x3C000000u : 0u);
            uint32_t p2 = (a2 != 0.0f ? 0x3C00u : 0u) | (b2 != 0.0f ? 0x3C000000u : 0u);
            uint32_t p3 = (a3 != 0.0f ? 0x3C00u : 0u) | (b3 != 0.0f ? 0x3C000000u : 0u);
            *(uint32_t*)(spb + 0*EFF) = p0;
            *(uint32_t*)(spb + 1*EFF) = p1;
            *(uint32_t*)(spb + 2*EFF) = p2;
            *(uint32_t*)(spb + 3*EFF) = p3;
        } else {
            int n = s_ent[sl] >> 1;
            float w = s_w[sl];
            float s[4][2] = {{a0,b0},{a1,b1},{a2,b2},{a3,b3}};
            #pragma unroll
            for (int t = 0; t < 4; ++t) {
                float* ob = out + ((size_t)t*NTOK + n)*DD + nc*128 + cp*2;
                if (s[t][0] != 0.0f) atomicAdd(ob,     w);
                if (s[t][1] != 0.0f) atomicAdd(ob + 1, w);
            }
        }
    }
#undef STAGE_CHUNK
}

#define S1_SMEM (3*4*TILE_B)                       // 221184 (3-stage) >= epilogue 67584
#define S2_SMEM (3*3*TILE_B)                       // 165888 >= 67584

extern "C" void kernel_launch(void* const* d_in, const int* in_sizes, int n_in,
                              void* d_out, int out_size) {
    const float* x  = (const float*)d_in[0];
    const int*   ei = (const int*)  d_in[1];
    const float* ew = (const float*)d_in[2];
    const float* up = (const float*)d_in[3];
    const float* dw = (const float*)d_in[4];
    float* out = (float*)d_out;
    (void)in_sizes; (void)n_in;

    cudaFuncSetAttribute(gemm_lif<1>, cudaFuncAttributeMaxDynamicSharedMemorySize, S1_SMEM);
    cudaFuncSetAttribute(gemm_lif<2>, cudaFuncAttributeMaxDynamicSharedMemorySize, S2_SMEM);

    cudaMemsetAsync(d_out, 0, (size_t)out_size * sizeof(float), 0);
    reset_kernel<<<1, 32>>>();
    route_kernel<<<NTOK/256, 256>>>(ei);
    split_all_kernel<<<(NX8 + NU8 + ND8 + 255)/256, 256>>>(x, up, dw);
    gemm_lif<1><<<dim3(CAP/MTOK, EFF/128, EE), 256, S1_SMEM>>>(ew, out);
    gemm_lif<2><<<dim3(CAP/MTOK, DD/128,  EE), 256, S2_SMEM>>>(ew, out);
}